// round 9
// baseline (speedup 1.0000x reference)
#include <cuda_runtime.h>
#include <cstdint>

// TreeAttention: N=8, T_DST=512, T_SRC=4096, HID=64, K=64, W0=64,
// SCALE_UP=2, OVERSAMPLE=1.5. One CTA (128 threads) per (n, a) row.
//
// Iterations 0..5: gather scores (8 threads/row, 2 rows in flight, indices
// precomputed in xs[]), tie-free rank, owner-thread child expansion into a
// 4096-bit bitmap, scan + sorted-unique extraction.
//
// Iteration 6 (specialized): entering it6, ws == tsrc, so ratio == 1
// (xs == pix), scale == 1 (identity expansion, no second child), tks == 64.
// The final mask is (top-64-by-score ∪ {pixel 0}) truncated to the 64
// smallest pixel values; slots are pixel-ascending, so this is a ballot +
// prefix-popc compaction of (pixel, score) pairs held in registers.
//
// Exactness: rintf (round-half-even), __fdiv_rn/__fmul_rn (no fast-math
// rewrites); ratio >= 1 => valid scores pairwise distinct => tie-free rank;
// NEG tail ranks to itself; pad pixel-0 bit set unconditionally.
//
// Occupancy: launch_bounds(128,12) caps regs at 40 -> 12 CTAs/SM (48 warps),
// hiding the barrier-phase latency chains with more co-resident CTAs.

#define NEGV  (-32000.0f)
#define FMINV (-1e30f)

__global__ __launch_bounds__(128, 12)
void tree_attn_kernel(const float* __restrict__ q,
                      const float* __restrict__ k,
                      const float* __restrict__ v,
                      float* __restrict__ out)
{
    const int row  = blockIdx.x;          // n*512 + a
    const int n    = row >> 9;
    const int a    = row & 511;
    const int t    = threadIdx.x;         // 0..127
    const int lane = t & 31;
    const int wid  = t >> 5;
    const int c8   = t & 7;               // chunk within row (8 threads/row)
    const int or8  = t >> 3;              // row slot (0..15)

    __shared__ __align__(16) float qs[64];
    __shared__ __align__(16) float sc[128];
    __shared__ __align__(16) float pr[64];
    __shared__ int      pix[128];
    __shared__ int      xs[128];          // precomputed gather indices
    __shared__ unsigned bm[128];          // 4096-bit value bitmap
    __shared__ int      wsum[4];

    const float  tsrc = (float)(3585 + a);        // T_SRC - T_DST + 1 + a
    const float* kb   = k + (size_t)n * (4096 * 64);

    if (t < 64) qs[t] = q[(size_t)row * 64 + t];
    {
        const float r0 = __fdiv_rn(tsrc, 64.0f);
        const int   p  = (t < 96) ? t : 0;
        pix[t] = p;
        xs[t]  = min((int)rintf(__fmul_rn((float)p, r0)), 4095);
    }
    bm[t] = 0u;
    __syncthreads();

    const float4 qa = ((const float4*)qs)[c8];
    const float4 qb = ((const float4*)qs)[c8 + 8];

    float ws = 64.0f;
    int   V  = 64;                        // valid prefix length (shared-state)

    #pragma unroll 1
    for (int it = 0; it < 6; ++it) {
        const int tks_max = (it == 0) ? 63 : 96;
        const int Zcur    = (it == 0) ? 96 : 128;

        // ---- A: scores, 8 threads/row, 2 rows in flight ----
        if (t >= V) sc[t] = NEGV;
        #pragma unroll 1
        for (int base = 0; base < V; base += 32) {
            const int  r0 = base + or8;
            const int  r1 = base + 16 + or8;
            const bool v0 = (r0 < V);
            const bool v1 = (r1 < V);
            float acc0 = 0.0f, acc1 = 0.0f;
            if (v0) {
                const float4* kr = (const float4*)(kb + (size_t)xs[r0] * 64);
                const float4 A = __ldg(kr + c8);
                const float4 B = __ldg(kr + c8 + 8);
                acc0  = A.x*qa.x + A.y*qa.y + A.z*qa.z + A.w*qa.w;
                acc0 += B.x*qb.x + B.y*qb.y + B.z*qb.z + B.w*qb.w;
            }
            if (v1) {
                const float4* kr = (const float4*)(kb + (size_t)xs[r1] * 64);
                const float4 A = __ldg(kr + c8);
                const float4 B = __ldg(kr + c8 + 8);
                acc1  = A.x*qa.x + A.y*qa.y + A.z*qa.z + A.w*qa.w;
                acc1 += B.x*qb.x + B.y*qb.y + B.z*qb.z + B.w*qb.w;
            }
            acc0 += __shfl_xor_sync(0xFFFFFFFFu, acc0, 1);
            acc1 += __shfl_xor_sync(0xFFFFFFFFu, acc1, 1);
            acc0 += __shfl_xor_sync(0xFFFFFFFFu, acc0, 2);
            acc1 += __shfl_xor_sync(0xFFFFFFFFu, acc1, 2);
            acc0 += __shfl_xor_sync(0xFFFFFFFFu, acc0, 4);
            acc1 += __shfl_xor_sync(0xFFFFFFFFu, acc1, 4);
            if (v0 && c8 == 0) sc[r0] = acc0;
            if (v1 && c8 == 0) sc[r1] = acc1;
        }
        __syncthreads();

        // ---- tks = clip(round(ws/tsrc*64*1.5), 1, min(ws-1, Z-1)) ----
        float tkf = rintf(__fmul_rn(__fmul_rn(__fdiv_rn(ws, tsrc), 64.0f), 1.5f));
        tkf = fminf(fmaxf(tkf, 1.0f), fminf(ws - 1.0f, (float)(Zcur - 1)));
        const int tks_eff = min((int)tkf, tks_max);

        const float wsn   = fminf(tsrc, __fmul_rn(ws, 2.0f));
        const float scale = __fdiv_rn(wsn, ws);

        // ---- B: rank + owner-thread expansion into bitmap ----
        if (t < V) {
            const float  sv  = sc[t];
            const int    nj4 = (V + 3) >> 2;  // sc tail is NEGV (< sv), safe
            const float4* s4 = (const float4*)sc;
            int rank = 0;
            #pragma unroll 4
            for (int j4 = 0; j4 < nj4; ++j4) {
                const float4 o = s4[j4];
                rank += (int)(o.x > sv);
                rank += (int)(o.y > sv);
                rank += (int)(o.z > sv);
                rank += (int)(o.w > sv);
            }
            if (rank < tks_max) {
                const int p  = pix[t];
                const int p0 = min((int)rintf(__fmul_rn((float)p, scale)), 4095);
                atomicOr(&bm[p0 >> 5], 1u << (p0 & 31));
                if (rank < tks_eff) {
                    const int p1 = (int)rintf(__fmul_rn((float)(p + 1), scale));
                    if (p1 - p0 >= 2) {
                        const int pv = min(p0 + 1, 4095);
                        atomicOr(&bm[pv >> 5], 1u << (pv & 31));
                    }
                }
            }
        }
        if (t == 127) atomicOr(&bm[0], 1u);   // pad zeros (tks_max < Z always)
        __syncthreads();

        // ---- C: popc + warp scan ----
        unsigned mw = bm[t];
        const int c = __popc(mw);
        int inc = c;
        #pragma unroll
        for (int d = 1; d < 32; d <<= 1) {
            const int o = __shfl_up_sync(0xFFFFFFFFu, inc, d);
            if (lane >= d) inc += o;
        }
        if (lane == 31) wsum[wid] = inc;
        __syncthreads();

        // ---- D: extract sorted-unique -> pix, next xs; clear bm ----
        int base2 = 0, total = 0;
        #pragma unroll
        for (int w2 = 0; w2 < 4; ++w2) {
            const int s = wsum[w2];
            if (w2 < wid) base2 += s;
            total += s;
        }
        const float ratio_n = __fdiv_rn(tsrc, wsn);   // next-iter gather ratio
        int off = base2 + inc - c;                    // exclusive prefix
        while (mw != 0u && off < 128) {
            const int b   = __ffs(mw) - 1;
            const int val = (t << 5) + b;
            pix[off] = val;
            xs[off]  = min((int)rintf(__fmul_rn((float)val, ratio_n)), 4095);
            mw &= (mw - 1u);
            ++off;
        }
        const int Vn = min(total, 128);
        if (t >= Vn) { pix[t] = 0; xs[t] = 0; }       // where(ps<0, 0, ps)
        bm[t] = 0u;
        __syncthreads();

        V  = Vn;
        ws = wsn;
    }

    // ==== it6 (ws == tsrc: ratio=1, scale=1, tks=64): direct top-64 ====
    {
        // scores at xs == pix
        if (t >= V) sc[t] = NEGV;
        #pragma unroll 1
        for (int base = 0; base < V; base += 32) {
            const int  r0 = base + or8;
            const int  r1 = base + 16 + or8;
            const bool v0 = (r0 < V);
            const bool v1 = (r1 < V);
            float acc0 = 0.0f, acc1 = 0.0f;
            if (v0) {
                const float4* kr = (const float4*)(kb + (size_t)xs[r0] * 64);
                const float4 A = __ldg(kr + c8);
                const float4 B = __ldg(kr + c8 + 8);
                acc0  = A.x*qa.x + A.y*qa.y + A.z*qa.z + A.w*qa.w;
                acc0 += B.x*qb.x + B.y*qb.y + B.z*qb.z + B.w*qb.w;
            }
            if (v1) {
                const float4* kr = (const float4*)(kb + (size_t)xs[r1] * 64);
                const float4 A = __ldg(kr + c8);
                const float4 B = __ldg(kr + c8 + 8);
                acc1  = A.x*qa.x + A.y*qa.y + A.z*qa.z + A.w*qa.w;
                acc1 += B.x*qb.x + B.y*qb.y + B.z*qb.z + B.w*qb.w;
            }
            acc0 += __shfl_xor_sync(0xFFFFFFFFu, acc0, 1);
            acc1 += __shfl_xor_sync(0xFFFFFFFFu, acc1, 1);
            acc0 += __shfl_xor_sync(0xFFFFFFFFu, acc0, 2);
            acc1 += __shfl_xor_sync(0xFFFFFFFFu, acc1, 2);
            acc0 += __shfl_xor_sync(0xFFFFFFFFu, acc0, 4);
            acc1 += __shfl_xor_sync(0xFFFFFFFFu, acc1, 4);
            if (v0 && c8 == 0) sc[r0] = acc0;
            if (v1 && c8 == 0) sc[r1] = acc1;
        }
        __syncthreads();

        // rank; winner = top-64 score, slot 0 (pixel 0) always included (pad)
        bool win = (t == 0);
        if (t < V) {
            const float  sv  = sc[t];
            const int    nj4 = (V + 3) >> 2;
            const float4* s4 = (const float4*)sc;
            int rank = 0;
            #pragma unroll 4
            for (int j4 = 0; j4 < nj4; ++j4) {
                const float4 o = s4[j4];
                rank += (int)(o.x > sv);
                rank += (int)(o.y > sv);
                rank += (int)(o.z > sv);
                rank += (int)(o.w > sv);
            }
            win = win || (rank < 64);
        }
        const int   myp = pix[t];         // to registers before compaction
        const float mys = sc[t];
        const unsigned wb = __ballot_sync(0xFFFFFFFFu, win);
        if (lane == 0) wsum[wid] = __popc(wb);
        __syncthreads();                  // rank reads of sc done; wsum ready

        int wbase = 0, total = 0;
        #pragma unroll
        for (int w2 = 0; w2 < 4; ++w2) {
            const int s = wsum[w2];
            if (w2 < wid) wbase += s;
            total += s;
        }
        const int cnt = min(total, 64);
        const int pos = wbase + __popc(wb & ((1u << lane) - 1u));
        // slots are pixel-ascending; truncation to 64 smallest pixels ==
        // dropping positions >= 64 (matches bitmap truncation incl. pad case)
        if (win && pos < 64) { pix[pos] = myp; sc[pos] = mys; }
        if (t >= cnt && t < 64) { pix[t] = 0; sc[t] = FMINV; }
        __syncthreads();
    }

    // ---- softmax numerators ----
    if (t < 64) {
        float mx = FMINV;
        const float4* s4 = (const float4*)sc;
        #pragma unroll
        for (int i = 0; i < 16; ++i) {
            const float4 vv = s4[i];
            mx = fmaxf(mx, fmaxf(fmaxf(vv.x, vv.y), fmaxf(vv.z, vv.w)));
        }
        pr[t] = __expf(sc[t] - mx);
    }
    __syncthreads();

    float denom = 0.0f;
    if (t < 64) {                         // only warps 0-1 need the sum
        const float4* p4 = (const float4*)pr;
        #pragma unroll
        for (int i = 0; i < 16; ++i) {
            const float4 vv = p4[i];
            denom += vv.x + vv.y + vv.z + vv.w;
        }
    }

    // ---- weighted V gather: 128 threads = 64 cols x 2 z-halves ----
    const float* vb  = v + (size_t)n * (4096 * 64);
    const int    col = t & 63;
    const int    zh  = t >> 6;
    float acc = 0.0f;
    #pragma unroll 4
    for (int z = zh * 32; z < zh * 32 + 32; ++z) {
        acc += pr[z] * __ldg(&vb[(size_t)pix[z] * 64 + col]);
    }
    sc[t] = acc;                          // pr/pix reads above precede any
    __syncthreads();                      // conflicting write; one barrier
    if (t < 64)                           // before the cross-warp read
        out[(size_t)row * 64 + t] = (sc[t] + sc[t + 64]) / denom;
}

extern "C" void kernel_launch(void* const* d_in, const int* in_sizes, int n_in,
                              void* d_out, int out_size)
{
    const float* q = (const float*)d_in[0];   // (8, 512, 64)
    const float* k = (const float*)d_in[1];   // (8, 4096, 64)
    const float* v = (const float*)d_in[2];   // (8, 4096, 64)
    float* out = (float*)d_out;               // (8, 512, 64)
    (void)in_sizes; (void)n_in; (void)out_size;

    tree_attn_kernel<<<8 * 512, 128>>>(q, k, v, out);
}

// round 10
// speedup vs baseline: 1.0340x; 1.0340x over previous
#include <cuda_runtime.h>
#include <cstdint>

// TreeAttention: N=8, T_DST=512, T_SRC=4096, HID=64, K=64, W0=64,
// SCALE_UP=2, OVERSAMPLE=1.5. One CTA (128 threads) per (n, a) row.
//
// Key change vs R8: the O(V^2) rank loop is replaced by exact top-k
// MEMBERSHIP via a 256-bucket histogram select on order-preserving uint
// keys (scores pairwise distinct => threshold set == stable-topk set):
//   - it0..5: dual-child set = top tks_eff; winner set = top tks_max when
//     V > tks_max (it0: 63<64, it5: 96<128), else all valid.
//   - it6: winner set = top 64; positions come from pixel-ascending
//     ballot compaction (score rank never needed for ordering).
// Warp 0 alone scans the histogram (descending suffix sums, 8 buckets per
// lane) to locate the crossing bucket; only crossing-bucket candidates do
// an in-bucket rank over a compacted list (C small).
//
// Exactness: rintf (round-half-even), __fdiv_rn/__fmul_rn; NEG-tail
// "winners" (when tks_max > V) contribute only child 0, covered by the
// unconditional bit-0 pad. launch_bounds(128,10): R9 showed 12 CTAs/40
// regs regresses; 48 regs / 10 CTAs is the sweet spot.

#define NEGV  (-32000.0f)
#define FMINV (-1e30f)

__device__ __forceinline__ unsigned sortable_u(float f) {
    unsigned i = __float_as_uint(f);
    return i ^ ((unsigned)((int)i >> 31) | 0x80000000u);
}

__global__ __launch_bounds__(128, 10)
void tree_attn_kernel(const float* __restrict__ q,
                      const float* __restrict__ k,
                      const float* __restrict__ v,
                      float* __restrict__ out)
{
    const int row  = blockIdx.x;          // n*512 + a
    const int n    = row >> 9;
    const int a    = row & 511;
    const int t    = threadIdx.x;         // 0..127
    const int lane = t & 31;
    const int wid  = t >> 5;
    const int c8   = t & 7;               // chunk within row (8 threads/row)
    const int or8  = t >> 3;              // row slot (0..15)

    __shared__ __align__(16) float qs[64];
    __shared__ __align__(16) float sc[128];
    __shared__ __align__(16) float pr[64];
    __shared__ int      pix[128];
    __shared__ int      xs[128];          // precomputed gather indices
    __shared__ unsigned bm[128];          // 4096-bit value bitmap
    __shared__ __align__(16) int hist[256];
    __shared__ unsigned cand1[128];
    __shared__ unsigned cand2[128];
    __shared__ int      wsum[4];
    __shared__ int      sel[6];           // bs1,m1,bs2,m2,cnt1,cnt2

    const float  tsrc = (float)(3585 + a);        // T_SRC - T_DST + 1 + a
    const float* kb   = k + (size_t)n * (4096 * 64);

    if (t < 64) qs[t] = q[(size_t)row * 64 + t];
    {
        const float r0 = __fdiv_rn(tsrc, 64.0f);
        const int   p  = (t < 96) ? t : 0;
        pix[t] = p;
        xs[t]  = min((int)rintf(__fmul_rn((float)p, r0)), 4095);
    }
    bm[t] = 0u;
    __syncthreads();

    const float4 qa = ((const float4*)qs)[c8];
    const float4 qb = ((const float4*)qs)[c8 + 8];

    float ws = 64.0f;
    int   V  = 64;                        // valid prefix length (shared-state)

    #pragma unroll 1
    for (int it = 0; it < 6; ++it) {
        const int tks_max = (it == 0) ? 63 : 96;
        const int Zcur    = (it == 0) ? 96 : 128;

        // ---- A: scores (8 threads/row, 2 rows in flight); zero hist ----
        hist[t] = 0; hist[t + 128] = 0;
        if (t < 2) sel[4 + t] = 0;
        #pragma unroll 1
        for (int base = 0; base < V; base += 32) {
            const int  r0 = base + or8;
            const int  r1 = base + 16 + or8;
            const bool v0 = (r0 < V);
            const bool v1 = (r1 < V);
            float acc0 = 0.0f, acc1 = 0.0f;
            if (v0) {
                const float4* kr = (const float4*)(kb + (size_t)xs[r0] * 64);
                const float4 A = __ldg(kr + c8);
                const float4 B = __ldg(kr + c8 + 8);
                acc0  = A.x*qa.x + A.y*qa.y + A.z*qa.z + A.w*qa.w;
                acc0 += B.x*qb.x + B.y*qb.y + B.z*qb.z + B.w*qb.w;
            }
            if (v1) {
                const float4* kr = (const float4*)(kb + (size_t)xs[r1] * 64);
                const float4 A = __ldg(kr + c8);
                const float4 B = __ldg(kr + c8 + 8);
                acc1  = A.x*qa.x + A.y*qa.y + A.z*qa.z + A.w*qa.w;
                acc1 += B.x*qb.x + B.y*qb.y + B.z*qb.z + B.w*qb.w;
            }
            acc0 += __shfl_xor_sync(0xFFFFFFFFu, acc0, 1);
            acc1 += __shfl_xor_sync(0xFFFFFFFFu, acc1, 1);
            acc0 += __shfl_xor_sync(0xFFFFFFFFu, acc0, 2);
            acc1 += __shfl_xor_sync(0xFFFFFFFFu, acc1, 2);
            acc0 += __shfl_xor_sync(0xFFFFFFFFu, acc0, 4);
            acc1 += __shfl_xor_sync(0xFFFFFFFFu, acc1, 4);
            if (v0 && c8 == 0) sc[r0] = acc0;
            if (v1 && c8 == 0) sc[r1] = acc1;
        }
        __syncthreads();                                     // B1

        // uniform params
        float tkf = rintf(__fmul_rn(__fmul_rn(__fdiv_rn(ws, tsrc), 64.0f), 1.5f));
        tkf = fminf(fmaxf(tkf, 1.0f), fminf(ws - 1.0f, (float)(Zcur - 1)));
        const int  k1     = min((int)tkf, tks_max);          // dual top-k
        const int  k2     = tks_max;                         // winner top-k
        const bool needK2 = (V > tks_max);
        const float wsn   = fminf(tsrc, __fmul_rn(ws, 2.0f));
        const float scale = __fdiv_rn(wsn, ws);

        const bool     valid  = (t < V);
        const float    sv     = sc[t];
        const unsigned u      = valid ? sortable_u(sv) : 0u;
        const int      bucket = (int)(u >> 24);
        if (valid) atomicAdd(&hist[bucket], 1);
        __syncthreads();                                     // B2

        // warp 0: descending suffix scan + crossing buckets
        if (wid == 0) {
            const int  base4 = 248 - (lane << 3);
            const int4 A4 = *(const int4*)&hist[base4];
            const int4 B4 = *(const int4*)&hist[base4 + 4];
            const int  s  = A4.x+A4.y+A4.z+A4.w + B4.x+B4.y+B4.z+B4.w;
            int incl = s;
            #pragma unroll
            for (int d = 1; d < 32; d <<= 1) {
                const int o = __shfl_up_sync(0xFFFFFFFFu, incl, d);
                if (lane >= d) incl += o;
            }
            int run = incl - s;
            const int hh[8] = {B4.w, B4.z, B4.y, B4.x, A4.w, A4.z, A4.y, A4.x};
            #pragma unroll
            for (int j = 0; j < 8; ++j) {
                const int b = 255 - ((lane << 3) + j);
                const int h = hh[j];
                if (run < k1 && run + h >= k1) { sel[0] = b; sel[1] = run; }
                if (needK2 && run < k2 && run + h >= k2) { sel[2] = b; sel[3] = run; }
                run += h;
            }
        }
        __syncthreads();                                     // B3

        const bool c1 = valid && (bucket == sel[0]);
        if (c1) cand1[atomicAdd(&sel[4], 1)] = u;
        const bool c2 = needK2 && valid && (bucket == sel[2]);
        if (c2) cand2[atomicAdd(&sel[5], 1)] = u;
        __syncthreads();                                     // B4

        // membership + expansion into bitmap
        bool winner = valid, dual = false;
        if (valid) {
            if (bucket > sel[0]) dual = true;
            else if (c1) {
                const int C = sel[4];
                int r = 0;
                for (int j = 0; j < C; ++j) r += (int)(cand1[j] > u);
                dual = (r < k1 - sel[1]);
            }
            if (needK2) {
                if (bucket > sel[2]) winner = true;
                else if (c2) {
                    const int C = sel[5];
                    int r = 0;
                    for (int j = 0; j < C; ++j) r += (int)(cand2[j] > u);
                    winner = (r < k2 - sel[3]);
                } else winner = false;
            }
        }
        if (winner) {
            const float pf = (float)pix[t];
            const int p0 = min((int)rintf(__fmul_rn(pf, scale)), 4095);
            atomicOr(&bm[p0 >> 5], 1u << (p0 & 31));
            if (dual) {
                const int p1 = (int)rintf(__fmul_rn(pf + 1.0f, scale));
                if (p1 - p0 >= 2) {
                    const int pv = min(p0 + 1, 4095);
                    atomicOr(&bm[pv >> 5], 1u << (pv & 31));
                }
            }
        }
        if (t == 127) atomicOr(&bm[0], 1u);   // pad zeros (tks_max < Z always)
        __syncthreads();                                     // B5

        // bitmap popc + warp scan
        unsigned mw = bm[t];
        const int c = __popc(mw);
        int inc = c;
        #pragma unroll
        for (int d = 1; d < 32; d <<= 1) {
            const int o = __shfl_up_sync(0xFFFFFFFFu, inc, d);
            if (lane >= d) inc += o;
        }
        if (lane == 31) wsum[wid] = inc;
        __syncthreads();                                     // B6

        // extraction -> pix, next xs; clear bm
        int base2 = 0, total = 0;
        #pragma unroll
        for (int w2 = 0; w2 < 4; ++w2) {
            const int s = wsum[w2];
            if (w2 < wid) base2 += s;
            total += s;
        }
        const float ratio_n = __fdiv_rn(tsrc, wsn);
        int off = base2 + inc - c;
        while (mw != 0u && off < 128) {
            const int b   = __ffs(mw) - 1;
            const int val = (t << 5) + b;
            pix[off] = val;
            xs[off]  = min((int)rintf(__fmul_rn((float)val, ratio_n)), 4095);
            mw &= (mw - 1u);
            ++off;
        }
        const int Vn = min(total, 128);
        if (t >= Vn) { pix[t] = 0; xs[t] = 0; }
        bm[t] = 0u;
        __syncthreads();                                     // B7

        V  = Vn;
        ws = wsn;
    }

    // ==== it6 (ws==tsrc: ratio=1, scale=1, tks=64): top-64 membership ====
    {
        hist[t] = 0; hist[t + 128] = 0;
        if (t == 0) sel[4] = 0;
        #pragma unroll 1
        for (int base = 0; base < V; base += 32) {
            const int  r0 = base + or8;
            const int  r1 = base + 16 + or8;
            const bool v0 = (r0 < V);
            const bool v1 = (r1 < V);
            float acc0 = 0.0f, acc1 = 0.0f;
            if (v0) {
                const float4* kr = (const float4*)(kb + (size_t)xs[r0] * 64);
                const float4 A = __ldg(kr + c8);
                const float4 B = __ldg(kr + c8 + 8);
                acc0  = A.x*qa.x + A.y*qa.y + A.z*qa.z + A.w*qa.w;
                acc0 += B.x*qb.x + B.y*qb.y + B.z*qb.z + B.w*qb.w;
            }
            if (v1) {
                const float4* kr = (const float4*)(kb + (size_t)xs[r1] * 64);
                const float4 A = __ldg(kr + c8);
                const float4 B = __ldg(kr + c8 + 8);
                acc1  = A.x*qa.x + A.y*qa.y + A.z*qa.z + A.w*qa.w;
                acc1 += B.x*qb.x + B.y*qb.y + B.z*qb.z + B.w*qb.w;
            }
            acc0 += __shfl_xor_sync(0xFFFFFFFFu, acc0, 1);
            acc1 += __shfl_xor_sync(0xFFFFFFFFu, acc1, 1);
            acc0 += __shfl_xor_sync(0xFFFFFFFFu, acc0, 2);
            acc1 += __shfl_xor_sync(0xFFFFFFFFu, acc1, 2);
            acc0 += __shfl_xor_sync(0xFFFFFFFFu, acc0, 4);
            acc1 += __shfl_xor_sync(0xFFFFFFFFu, acc1, 4);
            if (v0 && c8 == 0) sc[r0] = acc0;
            if (v1 && c8 == 0) sc[r1] = acc1;
        }
        __syncthreads();                                     // C1

        const bool     valid  = (t < V);
        const float    sv     = valid ? sc[t] : FMINV;
        const unsigned u      = valid ? sortable_u(sv) : 0u;
        const int      bucket = (int)(u >> 24);
        if (valid) atomicAdd(&hist[bucket], 1);
        __syncthreads();                                     // C2

        if (wid == 0) {
            const int  base4 = 248 - (lane << 3);
            const int4 A4 = *(const int4*)&hist[base4];
            const int4 B4 = *(const int4*)&hist[base4 + 4];
            const int  s  = A4.x+A4.y+A4.z+A4.w + B4.x+B4.y+B4.z+B4.w;
            int incl = s;
            #pragma unroll
            for (int d = 1; d < 32; d <<= 1) {
                const int o = __shfl_up_sync(0xFFFFFFFFu, incl, d);
                if (lane >= d) incl += o;
            }
            int run = incl - s;
            const int hh[8] = {B4.w, B4.z, B4.y, B4.x, A4.w, A4.z, A4.y, A4.x};
            #pragma unroll
            for (int j = 0; j < 8; ++j) {
                const int b = 255 - ((lane << 3) + j);
                const int h = hh[j];
                if (run < 64 && run + h >= 64) { sel[0] = b; sel[1] = run; }
                run += h;
            }
        }
        __syncthreads();                                     // C3

        const bool c1 = valid && (bucket == sel[0]);
        if (c1) cand1[atomicAdd(&sel[4], 1)] = u;
        __syncthreads();                                     // C4

        bool member = false;
        if (valid) {
            if (bucket > sel[0]) member = true;
            else if (c1) {
                const int C = sel[4];
                int r = 0;
                for (int j = 0; j < C; ++j) r += (int)(cand1[j] > u);
                member = (r < 64 - sel[1]);
            }
        }
        const bool  win = (t == 0) || member;   // slot 0 = pixel 0 pad
        const int   myp = pix[t];
        const float mys = sv;
        const unsigned wb = __ballot_sync(0xFFFFFFFFu, win);
        if (lane == 0) wsum[wid] = __popc(wb);
        __syncthreads();                                     // C5

        int wbase = 0, total = 0;
        #pragma unroll
        for (int w2 = 0; w2 < 4; ++w2) {
            const int s = wsum[w2];
            if (w2 < wid) wbase += s;
            total += s;
        }
        const int cnt = min(total, 64);
        const int pos = wbase + __popc(wb & ((1u << lane) - 1u));
        // slots pixel-ascending; keep the 64 smallest pixel values
        if (win && pos < 64) { pix[pos] = myp; sc[pos] = mys; }
        if (t >= cnt && t < 64) { pix[t] = 0; sc[t] = FMINV; }
        __syncthreads();                                     // C6
    }

    // ---- softmax numerators ----
    if (t < 64) {
        float mx = FMINV;
        const float4* s4 = (const float4*)sc;
        #pragma unroll
        for (int i = 0; i < 16; ++i) {
            const float4 vv = s4[i];
            mx = fmaxf(mx, fmaxf(fmaxf(vv.x, vv.y), fmaxf(vv.z, vv.w)));
        }
        pr[t] = __expf(sc[t] - mx);
    }
    __syncthreads();

    float denom = 0.0f;
    if (t < 64) {
        const float4* p4 = (const float4*)pr;
        #pragma unroll
        for (int i = 0; i < 16; ++i) {
            const float4 vv = p4[i];
            denom += vv.x + vv.y + vv.z + vv.w;
        }
    }

    // ---- weighted V gather: 128 threads = 64 cols x 2 z-halves ----
    const float* vb  = v + (size_t)n * (4096 * 64);
    const int    col = t & 63;
    const int    zh  = t >> 6;
    float acc = 0.0f;
    #pragma unroll 4
    for (int z = zh * 32; z < zh * 32 + 32; ++z) {
        acc += pr[z] * __ldg(&vb[(size_t)pix[z] * 64 + col]);
    }
    sc[t] = acc;
    __syncthreads();
    if (t < 64)
        out[(size_t)row * 64 + t] = (sc[t] + sc[t + 64]) / denom;
}

extern "C" void kernel_launch(void* const* d_in, const int* in_sizes, int n_in,
                              void* d_out, int out_size)
{
    const float* q = (const float*)d_in[0];   // (8, 512, 64)
    const float* k = (const float*)d_in[1];   // (8, 4096, 64)
    const float* v = (const float*)d_in[2];   // (8, 4096, 64)
    float* out = (float*)d_out;               // (8, 512, 64)
    (void)in_sizes; (void)n_in; (void)out_size;

    tree_attn_kernel<<<8 * 512, 128>>>(q, k, v, out);
}

// round 11
// speedup vs baseline: 1.1564x; 1.1184x over previous
#include <cuda_runtime.h>
#include <cstdint>

// TreeAttention: N=8, T_DST=512, T_SRC=4096, HID=64, K=64, W0=64,
// SCALE_UP=2, OVERSAMPLE=1.5. One CTA (128 threads) per (n, a) row.
//
// Top-k via 256-bucket histogram MEMBERSHIP select (scores pairwise
// distinct). Child expansion needs no sort/dedup: scale >= 1.75 every
// iteration and winner pixels are slot-ascending, so the emitted stream
// {child0(p), maybe child0(p)+1} (+ leading 0 if slot 0 lost) is already
// strictly increasing. Extraction = emit-count prefix scan + direct writes.
//
// it6 specialized: ws == tsrc -> ratio=1, scale=1, tks=64; final set =
// (top-64 by score ∪ {pixel 0}) truncated to 64 smallest pixels, done by
// ballot compaction of register-held (pixel, score) pairs.
//
// Exactness: rintf (round-half-even), __fdiv_rn/__fmul_rn; NEG-tail pads
// contribute only pixel 0 (always emitted). launch_bounds(128,10) = the
// R8/R9-validated occupancy sweet spot (48 regs, 10 CTAs/SM).

#define NEGV  (-32000.0f)
#define FMINV (-1e30f)

__device__ __forceinline__ unsigned sortable_u(float f) {
    unsigned i = __float_as_uint(f);
    return i ^ ((unsigned)((int)i >> 31) | 0x80000000u);
}

__global__ __launch_bounds__(128, 10)
void tree_attn_kernel(const float* __restrict__ q,
                      const float* __restrict__ k,
                      const float* __restrict__ v,
                      float* __restrict__ out)
{
    const int row  = blockIdx.x;          // n*512 + a
    const int n    = row >> 9;
    const int a    = row & 511;
    const int t    = threadIdx.x;         // 0..127
    const int lane = t & 31;
    const int wid  = t >> 5;
    const int c8   = t & 7;               // chunk within row (8 threads/row)
    const int or8  = t >> 3;              // row slot (0..15)

    __shared__ __align__(16) float qs[64];
    __shared__ __align__(16) float sc[128];
    __shared__ __align__(16) float pr[64];
    __shared__ int      pix[128];
    __shared__ int      xs[128];          // precomputed gather indices
    __shared__ __align__(16) int hist[256];
    __shared__ unsigned cand1[128];
    __shared__ unsigned cand2[128];
    __shared__ int      wsum[4];
    __shared__ int      sel[7];           // bs1,m1,bs2,m2,cnt1,cnt2,extra

    const float  tsrc = (float)(3585 + a);        // T_SRC - T_DST + 1 + a
    const float* kb   = k + (size_t)n * (4096 * 64);

    if (t < 64) qs[t] = q[(size_t)row * 64 + t];
    {
        const float r0 = __fdiv_rn(tsrc, 64.0f);
        const int   p  = (t < 96) ? t : 0;
        pix[t] = p;
        xs[t]  = min((int)rintf(__fmul_rn((float)p, r0)), 4095);
    }
    __syncthreads();

    const float4 qa = ((const float4*)qs)[c8];
    const float4 qb = ((const float4*)qs)[c8 + 8];

    float ws = 64.0f;
    int   V  = 64;                        // valid prefix length (shared-state)

    #pragma unroll 1
    for (int it = 0; it < 6; ++it) {
        const int tks_max = (it == 0) ? 63 : 96;
        const int Zcur    = (it == 0) ? 96 : 128;

        // ---- A: scores (8 threads/row, 2 rows in flight); zero hist ----
        hist[t] = 0; hist[t + 128] = 0;
        if (t < 2) sel[4 + t] = 0;
        #pragma unroll 1
        for (int base = 0; base < V; base += 32) {
            const int  r0 = base + or8;
            const int  r1 = base + 16 + or8;
            const bool v0 = (r0 < V);
            const bool v1 = (r1 < V);
            float acc0 = 0.0f, acc1 = 0.0f;
            if (v0) {
                const float4* kr = (const float4*)(kb + (size_t)xs[r0] * 64);
                const float4 A = __ldg(kr + c8);
                const float4 B = __ldg(kr + c8 + 8);
                acc0  = A.x*qa.x + A.y*qa.y + A.z*qa.z + A.w*qa.w;
                acc0 += B.x*qb.x + B.y*qb.y + B.z*qb.z + B.w*qb.w;
            }
            if (v1) {
                const float4* kr = (const float4*)(kb + (size_t)xs[r1] * 64);
                const float4 A = __ldg(kr + c8);
                const float4 B = __ldg(kr + c8 + 8);
                acc1  = A.x*qa.x + A.y*qa.y + A.z*qa.z + A.w*qa.w;
                acc1 += B.x*qb.x + B.y*qb.y + B.z*qb.z + B.w*qb.w;
            }
            acc0 += __shfl_xor_sync(0xFFFFFFFFu, acc0, 1);
            acc1 += __shfl_xor_sync(0xFFFFFFFFu, acc1, 1);
            acc0 += __shfl_xor_sync(0xFFFFFFFFu, acc0, 2);
            acc1 += __shfl_xor_sync(0xFFFFFFFFu, acc1, 2);
            acc0 += __shfl_xor_sync(0xFFFFFFFFu, acc0, 4);
            acc1 += __shfl_xor_sync(0xFFFFFFFFu, acc1, 4);
            if (v0 && c8 == 0) sc[r0] = acc0;
            if (v1 && c8 == 0) sc[r1] = acc1;
        }
        __syncthreads();                                     // B1

        // uniform params
        float tkf = rintf(__fmul_rn(__fmul_rn(__fdiv_rn(ws, tsrc), 64.0f), 1.5f));
        tkf = fminf(fmaxf(tkf, 1.0f), fminf(ws - 1.0f, (float)(Zcur - 1)));
        const int  k1     = min((int)tkf, tks_max);          // dual top-k
        const int  k2     = tks_max;                         // winner top-k
        const bool needK2 = (V > tks_max);
        const float wsn   = fminf(tsrc, __fmul_rn(ws, 2.0f));
        const float scale = __fdiv_rn(wsn, ws);

        const bool     valid  = (t < V);
        const float    sv     = sc[t];
        const unsigned u      = valid ? sortable_u(sv) : 0u;
        const int      bucket = (int)(u >> 24);
        if (valid) atomicAdd(&hist[bucket], 1);
        __syncthreads();                                     // B2

        // warp 0: descending suffix scan + crossing buckets
        if (wid == 0) {
            const int  base4 = 248 - (lane << 3);
            const int4 A4 = *(const int4*)&hist[base4];
            const int4 B4 = *(const int4*)&hist[base4 + 4];
            const int  s  = A4.x+A4.y+A4.z+A4.w + B4.x+B4.y+B4.z+B4.w;
            int incl = s;
            #pragma unroll
            for (int d = 1; d < 32; d <<= 1) {
                const int o = __shfl_up_sync(0xFFFFFFFFu, incl, d);
                if (lane >= d) incl += o;
            }
            int run = incl - s;
            const int hh[8] = {B4.w, B4.z, B4.y, B4.x, A4.w, A4.z, A4.y, A4.x};
            #pragma unroll
            for (int j = 0; j < 8; ++j) {
                const int b = 255 - ((lane << 3) + j);
                const int h = hh[j];
                if (run < k1 && run + h >= k1) { sel[0] = b; sel[1] = run; }
                if (needK2 && run < k2 && run + h >= k2) { sel[2] = b; sel[3] = run; }
                run += h;
            }
        }
        __syncthreads();                                     // B3

        const bool c1 = valid && (bucket == sel[0]);
        if (c1) cand1[atomicAdd(&sel[4], 1)] = u;
        const bool c2 = needK2 && valid && (bucket == sel[2]);
        if (c2) cand2[atomicAdd(&sel[5], 1)] = u;
        __syncthreads();                                     // B4

        // ---- membership + monotone child emission ----
        bool winner = valid, dual = false;
        if (valid) {
            if (bucket > sel[0]) dual = true;
            else if (c1) {
                const int C = sel[4];
                int r = 0;
                for (int j = 0; j < C; ++j) r += (int)(cand1[j] > u);
                dual = (r < k1 - sel[1]);
            }
            if (needK2) {
                if (bucket > sel[2]) winner = true;
                else if (c2) {
                    const int C = sel[5];
                    int r = 0;
                    for (int j = 0; j < C; ++j) r += (int)(cand2[j] > u);
                    winner = (r < k2 - sel[3]);
                } else winner = false;
            }
        }
        int e = 0, p0 = 0;
        if (winner) {
            const float pf = (float)pix[t];
            p0 = min((int)rintf(__fmul_rn(pf, scale)), 4095);
            e = 1;
            if (dual) {
                const int p1 = (int)rintf(__fmul_rn(pf + 1.0f, scale));
                if (p1 - p0 >= 2) e = 2;
            }
        }
        // emit-count scan; slot-0-loser flag (prepended 0)
        int incl = e;
        #pragma unroll
        for (int d = 1; d < 32; d <<= 1) {
            const int o = __shfl_up_sync(0xFFFFFFFFu, incl, d);
            if (lane >= d) incl += o;
        }
        if (lane == 31) wsum[wid] = incl;
        if (t == 0) sel[6] = winner ? 0 : 1;
        __syncthreads();                                     // B5

        const int extra = sel[6];
        int base2 = extra, total = extra;
        #pragma unroll
        for (int w2 = 0; w2 < 4; ++w2) {
            const int s = wsum[w2];
            if (w2 < wid) base2 += s;
            total += s;
        }
        const float ratio_n = __fdiv_rn(tsrc, wsn);
        const int pos = base2 + incl - e;                    // exclusive
        if (extra && t == 0) { pix[0] = 0; xs[0] = 0; }
        if (e >= 1 && pos < 128) {
            pix[pos] = p0;
            xs[pos]  = min((int)rintf(__fmul_rn((float)p0, ratio_n)), 4095);
        }
        if (e == 2 && pos + 1 < 128) {
            const int pv = p0 + 1;
            pix[pos + 1] = pv;
            xs[pos + 1]  = min((int)rintf(__fmul_rn((float)pv, ratio_n)), 4095);
        }
        const int Vn = min(total, 128);
        if (t >= Vn) { pix[t] = 0; xs[t] = 0; }
        __syncthreads();                                     // B6

        V  = Vn;
        ws = wsn;
    }

    // ==== it6 (ws==tsrc: ratio=1, scale=1, tks=64): top-64 membership ====
    {
        hist[t] = 0; hist[t + 128] = 0;
        if (t == 0) sel[4] = 0;
        #pragma unroll 1
        for (int base = 0; base < V; base += 32) {
            const int  r0 = base + or8;
            const int  r1 = base + 16 + or8;
            const bool v0 = (r0 < V);
            const bool v1 = (r1 < V);
            float acc0 = 0.0f, acc1 = 0.0f;
            if (v0) {
                const float4* kr = (const float4*)(kb + (size_t)xs[r0] * 64);
                const float4 A = __ldg(kr + c8);
                const float4 B = __ldg(kr + c8 + 8);
                acc0  = A.x*qa.x + A.y*qa.y + A.z*qa.z + A.w*qa.w;
                acc0 += B.x*qb.x + B.y*qb.y + B.z*qb.z + B.w*qb.w;
            }
            if (v1) {
                const float4* kr = (const float4*)(kb + (size_t)xs[r1] * 64);
                const float4 A = __ldg(kr + c8);
                const float4 B = __ldg(kr + c8 + 8);
                acc1  = A.x*qa.x + A.y*qa.y + A.z*qa.z + A.w*qa.w;
                acc1 += B.x*qb.x + B.y*qb.y + B.z*qb.z + B.w*qb.w;
            }
            acc0 += __shfl_xor_sync(0xFFFFFFFFu, acc0, 1);
            acc1 += __shfl_xor_sync(0xFFFFFFFFu, acc1, 1);
            acc0 += __shfl_xor_sync(0xFFFFFFFFu, acc0, 2);
            acc1 += __shfl_xor_sync(0xFFFFFFFFu, acc1, 2);
            acc0 += __shfl_xor_sync(0xFFFFFFFFu, acc0, 4);
            acc1 += __shfl_xor_sync(0xFFFFFFFFu, acc1, 4);
            if (v0 && c8 == 0) sc[r0] = acc0;
            if (v1 && c8 == 0) sc[r1] = acc1;
        }
        __syncthreads();                                     // C1

        const bool     valid  = (t < V);
        const float    sv     = valid ? sc[t] : FMINV;
        const unsigned u      = valid ? sortable_u(sv) : 0u;
        const int      bucket = (int)(u >> 24);
        if (valid) atomicAdd(&hist[bucket], 1);
        __syncthreads();                                     // C2

        if (wid == 0) {
            const int  base4 = 248 - (lane << 3);
            const int4 A4 = *(const int4*)&hist[base4];
            const int4 B4 = *(const int4*)&hist[base4 + 4];
            const int  s  = A4.x+A4.y+A4.z+A4.w + B4.x+B4.y+B4.z+B4.w;
            int incl = s;
            #pragma unroll
            for (int d = 1; d < 32; d <<= 1) {
                const int o = __shfl_up_sync(0xFFFFFFFFu, incl, d);
                if (lane >= d) incl += o;
            }
            int run = incl - s;
            const int hh[8] = {B4.w, B4.z, B4.y, B4.x, A4.w, A4.z, A4.y, A4.x};
            #pragma unroll
            for (int j = 0; j < 8; ++j) {
                const int b = 255 - ((lane << 3) + j);
                const int h = hh[j];
                if (run < 64 && run + h >= 64) { sel[0] = b; sel[1] = run; }
                run += h;
            }
        }
        __syncthreads();                                     // C3

        const bool c1 = valid && (bucket == sel[0]);
        if (c1) cand1[atomicAdd(&sel[4], 1)] = u;
        __syncthreads();                                     // C4

        bool member = false;
        if (valid) {
            if (bucket > sel[0]) member = true;
            else if (c1) {
                const int C = sel[4];
                int r = 0;
                for (int j = 0; j < C; ++j) r += (int)(cand1[j] > u);
                member = (r < 64 - sel[1]);
            }
        }
        const bool  win = (t == 0) || member;   // slot 0 = pixel 0 pad
        const int   myp = pix[t];
        const float mys = sv;
        const unsigned wb = __ballot_sync(0xFFFFFFFFu, win);
        if (lane == 0) wsum[wid] = __popc(wb);
        __syncthreads();                                     // C5

        int wbase = 0, total = 0;
        #pragma unroll
        for (int w2 = 0; w2 < 4; ++w2) {
            const int s = wsum[w2];
            if (w2 < wid) wbase += s;
            total += s;
        }
        const int cnt = min(total, 64);
        const int pos = wbase + __popc(wb & ((1u << lane) - 1u));
        // slots pixel-ascending; keep the 64 smallest pixel values
        if (win && pos < 64) { pix[pos] = myp; sc[pos] = mys; }
        if (t >= cnt && t < 64) { pix[t] = 0; sc[t] = FMINV; }
        __syncthreads();                                     // C6
    }

    // ---- softmax numerators ----
    if (t < 64) {
        float mx = FMINV;
        const float4* s4 = (const float4*)sc;
        #pragma unroll
        for (int i = 0; i < 16; ++i) {
            const float4 vv = s4[i];
            mx = fmaxf(mx, fmaxf(fmaxf(vv.x, vv.y), fmaxf(vv.z, vv.w)));
        }
        pr[t] = __expf(sc[t] - mx);
    }
    __syncthreads();

    float denom = 0.0f;
    if (t < 64) {
        const float4* p4 = (const float4*)pr;
        #pragma unroll
        for (int i = 0; i < 16; ++i) {
            const float4 vv = p4[i];
            denom += vv.x + vv.y + vv.z + vv.w;
        }
    }

    // ---- weighted V gather: 128 threads = 64 cols x 2 z-halves ----
    const float* vb  = v + (size_t)n * (4096 * 64);
    const int    col = t & 63;
    const int    zh  = t >> 6;
    float acc = 0.0f;
    #pragma unroll 4
    for (int z = zh * 32; z < zh * 32 + 32; ++z) {
        acc += pr[z] * __ldg(&vb[(size_t)pix[z] * 64 + col]);
    }
    sc[t] = acc;
    __syncthreads();
    if (t < 64)
        out[(size_t)row * 64 + t] = (sc[t] + sc[t + 64]) / denom;
}

extern "C" void kernel_launch(void* const* d_in, const int* in_sizes, int n_in,
                              void* d_out, int out_size)
{
    const float* q = (const float*)d_in[0];   // (8, 512, 64)
    const float* k = (const float*)d_in[1];   // (8, 4096, 64)
    const float* v = (const float*)d_in[2];   // (8, 4096, 64)
    float* out = (float*)d_out;               // (8, 512, 64)
    (void)in_sizes; (void)n_in; (void)out_size;

    tree_attn_kernel<<<8 * 512, 128>>>(q, k, v, out);
}

// round 12
// speedup vs baseline: 1.3665x; 1.1817x over previous
#include <cuda_runtime.h>
#include <cstdint>

// TreeAttention: N=8, T_DST=512, T_SRC=4096, HID=64, K=64, W0=64,
// SCALE_UP=2, OVERSAMPLE=1.5. One CTA (128 threads) per (n, a) row.
//
// Score caching across iterations: child0's gather index equals its
// parent's index BIT-EXACTLY (scale=2 binade scaling for it0..4; at it5
// scale == ratio so child0 == xs_parent and it6's ratio is exactly 1).
// So child0 scores are copied at placement; only DUAL children (and the
// initial 64 rows) are ever gathered, via a worklist wl[0..wlcnt).
// Pixel-0 slot is invariant (pix[0]=0, xs[0]=0, sc[0]=q.k[0] constant).
//
// Top-k via 256-bucket histogram MEMBERSHIP select (scores pairwise
// distinct). Child emission is monotone (scale>=1.75, slots ascending)
// => emitted stream already sorted-unique; placement = emit-count scan.
//
// it6 specialized: ws==tsrc -> ratio=1, scale=1, tks=64; final set =
// (top-64 by score ∪ {pixel 0}) truncated to 64 smallest pixels via
// ballot compaction. Exactness: rintf, __fdiv_rn/__fmul_rn throughout.

#define NEGV  (-32000.0f)
#define FMINV (-1e30f)

__device__ __forceinline__ unsigned sortable_u(float f) {
    unsigned i = __float_as_uint(f);
    return i ^ ((unsigned)((int)i >> 31) | 0x80000000u);
}

__global__ __launch_bounds__(128, 10)
void tree_attn_kernel(const float* __restrict__ q,
                      const float* __restrict__ k,
                      const float* __restrict__ v,
                      float* __restrict__ out)
{
    const int row  = blockIdx.x;          // n*512 + a
    const int n    = row >> 9;
    const int a    = row & 511;
    const int t    = threadIdx.x;         // 0..127
    const int lane = t & 31;
    const int wid  = t >> 5;
    const int c8   = t & 7;               // chunk within row (8 threads/row)
    const int or8  = t >> 3;              // row slot (0..15)

    __shared__ __align__(16) float qs[64];
    __shared__ __align__(16) float sc[128];
    __shared__ __align__(16) float pr[64];
    __shared__ int      pix[128];
    __shared__ int      xs[128];          // gather indices
    __shared__ __align__(16) int hist[256];
    __shared__ unsigned cand1[128];
    __shared__ unsigned cand2[128];
    __shared__ int      wl[128];          // uncached-slot worklist
    __shared__ int      wlcnt;
    __shared__ int      wsum[4];
    __shared__ int      sel[7];           // bs1,m1,bs2,m2,cnt1,cnt2,extra

    const float  tsrc = (float)(3585 + a);        // T_SRC - T_DST + 1 + a
    const float* kb   = k + (size_t)n * (4096 * 64);

    if (t < 64) qs[t] = q[(size_t)row * 64 + t];
    {
        const float r0 = __fdiv_rn(tsrc, 64.0f);
        const int   p  = (t < 96) ? t : 0;
        pix[t] = p;
        xs[t]  = min((int)rintf(__fmul_rn((float)p, r0)), 4095);
    }
    if (t < 64) wl[t] = t;                // initial rows all uncached
    if (t == 0) wlcnt = 64;
    __syncthreads();

    const float4 qa = ((const float4*)qs)[c8];
    const float4 qb = ((const float4*)qs)[c8 + 8];

    float ws = 64.0f;
    int   V  = 64;                        // valid prefix length (shared-state)

    #pragma unroll 1
    for (int it = 0; it < 6; ++it) {
        const int tks_max = (it == 0) ? 63 : 96;
        const int Zcur    = (it == 0) ? 96 : 128;

        // ---- A: gather ONLY uncached rows (worklist); zero hist ----
        const int U = wlcnt;              // read before any thread passes B1
        if (t >= V) sc[t] = NEGV;
        hist[t] = 0; hist[t + 128] = 0;
        if (t < 2) sel[4 + t] = 0;
        #pragma unroll 1
        for (int base = 0; base < U; base += 32) {
            const int  i0 = base + or8;
            const int  i1 = base + 16 + or8;
            const bool v0 = (i0 < U);
            const bool v1 = (i1 < U);
            const int  r0 = v0 ? wl[i0] : 0;
            const int  r1 = v1 ? wl[i1] : 0;
            float acc0 = 0.0f, acc1 = 0.0f;
            if (v0) {
                const float4* kr = (const float4*)(kb + (size_t)xs[r0] * 64);
                const float4 A = __ldg(kr + c8);
                const float4 B = __ldg(kr + c8 + 8);
                acc0  = A.x*qa.x + A.y*qa.y + A.z*qa.z + A.w*qa.w;
                acc0 += B.x*qb.x + B.y*qb.y + B.z*qb.z + B.w*qb.w;
            }
            if (v1) {
                const float4* kr = (const float4*)(kb + (size_t)xs[r1] * 64);
                const float4 A = __ldg(kr + c8);
                const float4 B = __ldg(kr + c8 + 8);
                acc1  = A.x*qa.x + A.y*qa.y + A.z*qa.z + A.w*qa.w;
                acc1 += B.x*qb.x + B.y*qb.y + B.z*qb.z + B.w*qb.w;
            }
            acc0 += __shfl_xor_sync(0xFFFFFFFFu, acc0, 1);
            acc1 += __shfl_xor_sync(0xFFFFFFFFu, acc1, 1);
            acc0 += __shfl_xor_sync(0xFFFFFFFFu, acc0, 2);
            acc1 += __shfl_xor_sync(0xFFFFFFFFu, acc1, 2);
            acc0 += __shfl_xor_sync(0xFFFFFFFFu, acc0, 4);
            acc1 += __shfl_xor_sync(0xFFFFFFFFu, acc1, 4);
            if (v0 && c8 == 0) sc[r0] = acc0;
            if (v1 && c8 == 0) sc[r1] = acc1;
        }
        __syncthreads();                                     // B1
        if (t == 0) wlcnt = 0;            // safe: all reads of wl/U done

        // uniform params
        float tkf = rintf(__fmul_rn(__fmul_rn(__fdiv_rn(ws, tsrc), 64.0f), 1.5f));
        tkf = fminf(fmaxf(tkf, 1.0f), fminf(ws - 1.0f, (float)(Zcur - 1)));
        const int  k1     = min((int)tkf, tks_max);          // dual top-k
        const int  k2     = tks_max;                         // winner top-k
        const bool needK2 = (V > tks_max);
        const float wsn   = fminf(tsrc, __fmul_rn(ws, 2.0f));
        const float scale = __fdiv_rn(wsn, ws);

        const bool     valid  = (t < V);
        const float    sv     = sc[t];
        const unsigned u      = valid ? sortable_u(sv) : 0u;
        const int      bucket = (int)(u >> 24);
        if (valid) atomicAdd(&hist[bucket], 1);
        __syncthreads();                                     // B2

        // warp 0: descending suffix scan + crossing buckets
        if (wid == 0) {
            const int  base4 = 248 - (lane << 3);
            const int4 A4 = *(const int4*)&hist[base4];
            const int4 B4 = *(const int4*)&hist[base4 + 4];
            const int  s  = A4.x+A4.y+A4.z+A4.w + B4.x+B4.y+B4.z+B4.w;
            int incl0 = s;
            #pragma unroll
            for (int d = 1; d < 32; d <<= 1) {
                const int o = __shfl_up_sync(0xFFFFFFFFu, incl0, d);
                if (lane >= d) incl0 += o;
            }
            int run = incl0 - s;
            const int hh[8] = {B4.w, B4.z, B4.y, B4.x, A4.w, A4.z, A4.y, A4.x};
            #pragma unroll
            for (int j = 0; j < 8; ++j) {
                const int b = 255 - ((lane << 3) + j);
                const int h = hh[j];
                if (run < k1 && run + h >= k1) { sel[0] = b; sel[1] = run; }
                if (needK2 && run < k2 && run + h >= k2) { sel[2] = b; sel[3] = run; }
                run += h;
            }
        }
        __syncthreads();                                     // B3

        const bool c1 = valid && (bucket == sel[0]);
        if (c1) cand1[atomicAdd(&sel[4], 1)] = u;
        const bool c2 = needK2 && valid && (bucket == sel[2]);
        if (c2) cand2[atomicAdd(&sel[5], 1)] = u;
        __syncthreads();                                     // B4

        // ---- membership + monotone child emission ----
        bool winner = valid, dual = false;
        if (valid) {
            if (bucket > sel[0]) dual = true;
            else if (c1) {
                const int C = sel[4];
                int r = 0;
                for (int j = 0; j < C; ++j) r += (int)(cand1[j] > u);
                dual = (r < k1 - sel[1]);
            }
            if (needK2) {
                if (bucket > sel[2]) winner = true;
                else if (c2) {
                    const int C = sel[5];
                    int r = 0;
                    for (int j = 0; j < C; ++j) r += (int)(cand2[j] > u);
                    winner = (r < k2 - sel[3]);
                } else winner = false;
            }
        }
        int e = 0, p0 = 0;
        if (winner) {
            const float pf = (float)pix[t];
            p0 = min((int)rintf(__fmul_rn(pf, scale)), 4095);
            e = 1;
            if (dual) {
                const int p1 = (int)rintf(__fmul_rn(pf + 1.0f, scale));
                if (p1 - p0 >= 2) e = 2;
            }
        }
        int incl = e;
        #pragma unroll
        for (int d = 1; d < 32; d <<= 1) {
            const int o = __shfl_up_sync(0xFFFFFFFFu, incl, d);
            if (lane >= d) incl += o;
        }
        if (lane == 31) wsum[wid] = incl;
        if (t == 0) sel[6] = winner ? 0 : 1;
        __syncthreads();                                     // B5

        const int extra = sel[6];
        int base2 = extra, total = extra;
        #pragma unroll
        for (int w2 = 0; w2 < 4; ++w2) {
            const int s = wsum[w2];
            if (w2 < wid) base2 += s;
            total += s;
        }
        const float ratio_n = __fdiv_rn(tsrc, wsn);
        const int pos = base2 + incl - e;                    // exclusive
        // prepended pixel-0: sc[0] already holds q.k[0] (slot-0 invariant)
        if (extra && t == 0) { pix[0] = 0; xs[0] = 0; }
        if (e >= 1 && pos < 128) {
            pix[pos] = p0;
            xs[pos]  = min((int)rintf(__fmul_rn((float)p0, ratio_n)), 4095);
            sc[pos]  = sv;                // cached: x_child == x_parent exact
        }
        if (e == 2 && pos + 1 < 128) {
            const int pv = p0 + 1;
            pix[pos + 1] = pv;
            xs[pos + 1]  = min((int)rintf(__fmul_rn((float)pv, ratio_n)), 4095);
            wl[atomicAdd(&wlcnt, 1)] = pos + 1;   // uncached: gather next iter
        }
        const int Vn = min(total, 128);
        if (t >= Vn) { pix[t] = 0; xs[t] = 0; }
        __syncthreads();                                     // B6

        V  = Vn;
        ws = wsn;
    }

    // ==== it6 (ws==tsrc: ratio=1, scale=1, tks=64): top-64 membership ====
    {
        const int U = wlcnt;
        hist[t] = 0; hist[t + 128] = 0;
        if (t == 0) sel[4] = 0;
        #pragma unroll 1
        for (int base = 0; base < U; base += 32) {
            const int  i0 = base + or8;
            const int  i1 = base + 16 + or8;
            const bool v0 = (i0 < U);
            const bool v1 = (i1 < U);
            const int  r0 = v0 ? wl[i0] : 0;
            const int  r1 = v1 ? wl[i1] : 0;
            float acc0 = 0.0f, acc1 = 0.0f;
            if (v0) {
                const float4* kr = (const float4*)(kb + (size_t)xs[r0] * 64);
                const float4 A = __ldg(kr + c8);
                const float4 B = __ldg(kr + c8 + 8);
                acc0  = A.x*qa.x + A.y*qa.y + A.z*qa.z + A.w*qa.w;
                acc0 += B.x*qb.x + B.y*qb.y + B.z*qb.z + B.w*qb.w;
            }
            if (v1) {
                const float4* kr = (const float4*)(kb + (size_t)xs[r1] * 64);
                const float4 A = __ldg(kr + c8);
                const float4 B = __ldg(kr + c8 + 8);
                acc1  = A.x*qa.x + A.y*qa.y + A.z*qa.z + A.w*qa.w;
                acc1 += B.x*qb.x + B.y*qb.y + B.z*qb.z + B.w*qb.w;
            }
            acc0 += __shfl_xor_sync(0xFFFFFFFFu, acc0, 1);
            acc1 += __shfl_xor_sync(0xFFFFFFFFu, acc1, 1);
            acc0 += __shfl_xor_sync(0xFFFFFFFFu, acc0, 2);
            acc1 += __shfl_xor_sync(0xFFFFFFFFu, acc1, 2);
            acc0 += __shfl_xor_sync(0xFFFFFFFFu, acc0, 4);
            acc1 += __shfl_xor_sync(0xFFFFFFFFu, acc1, 4);
            if (v0 && c8 == 0) sc[r0] = acc0;
            if (v1 && c8 == 0) sc[r1] = acc1;
        }
        __syncthreads();                                     // C1

        const bool     valid  = (t < V);
        const float    sv     = valid ? sc[t] : FMINV;
        const unsigned u      = valid ? sortable_u(sv) : 0u;
        const int      bucket = (int)(u >> 24);
        if (valid) atomicAdd(&hist[bucket], 1);
        __syncthreads();                                     // C2

        if (wid == 0) {
            const int  base4 = 248 - (lane << 3);
            const int4 A4 = *(const int4*)&hist[base4];
            const int4 B4 = *(const int4*)&hist[base4 + 4];
            const int  s  = A4.x+A4.y+A4.z+A4.w + B4.x+B4.y+B4.z+B4.w;
            int incl0 = s;
            #pragma unroll
            for (int d = 1; d < 32; d <<= 1) {
                const int o = __shfl_up_sync(0xFFFFFFFFu, incl0, d);
                if (lane >= d) incl0 += o;
            }
            int run = incl0 - s;
            const int hh[8] = {B4.w, B4.z, B4.y, B4.x, A4.w, A4.z, A4.y, A4.x};
            #pragma unroll
            for (int j = 0; j < 8; ++j) {
                const int b = 255 - ((lane << 3) + j);
                const int h = hh[j];
                if (run < 64 && run + h >= 64) { sel[0] = b; sel[1] = run; }
                run += h;
            }
        }
        __syncthreads();                                     // C3

        const bool c1 = valid && (bucket == sel[0]);
        if (c1) cand1[atomicAdd(&sel[4], 1)] = u;
        __syncthreads();                                     // C4

        bool member = false;
        if (valid) {
            if (bucket > sel[0]) member = true;
            else if (c1) {
                const int C = sel[4];
                int r = 0;
                for (int j = 0; j < C; ++j) r += (int)(cand1[j] > u);
                member = (r < 64 - sel[1]);
            }
        }
        const bool  win = (t == 0) || member;   // slot 0 = pixel 0 pad
        const int   myp = pix[t];
        const float mys = sv;
        const unsigned wb = __ballot_sync(0xFFFFFFFFu, win);
        if (lane == 0) wsum[wid] = __popc(wb);
        __syncthreads();                                     // C5

        int wbase = 0, total = 0;
        #pragma unroll
        for (int w2 = 0; w2 < 4; ++w2) {
            const int s = wsum[w2];
            if (w2 < wid) wbase += s;
            total += s;
        }
        const int cnt = min(total, 64);
        const int pos = wbase + __popc(wb & ((1u << lane) - 1u));
        // slots pixel-ascending; keep the 64 smallest pixel values
        if (win && pos < 64) { pix[pos] = myp; sc[pos] = mys; }
        if (t >= cnt && t < 64) { pix[t] = 0; sc[t] = FMINV; }
        __syncthreads();                                     // C6
    }

    // ---- softmax numerators ----
    if (t < 64) {
        float mx = FMINV;
        const float4* s4 = (const float4*)sc;
        #pragma unroll
        for (int i = 0; i < 16; ++i) {
            const float4 vv = s4[i];
            mx = fmaxf(mx, fmaxf(fmaxf(vv.x, vv.y), fmaxf(vv.z, vv.w)));
        }
        pr[t] = __expf(sc[t] - mx);
    }
    __syncthreads();

    float denom = 0.0f;
    if (t < 64) {
        const float4* p4 = (const float4*)pr;
        #pragma unroll
        for (int i = 0; i < 16; ++i) {
            const float4 vv = p4[i];
            denom += vv.x + vv.y + vv.z + vv.w;
        }
    }

    // ---- weighted V gather: 128 threads = 64 cols x 2 z-halves ----
    const float* vb  = v + (size_t)n * (4096 * 64);
    const int    col = t & 63;
    const int    zh  = t >> 6;
    float acc = 0.0f;
    #pragma unroll 4
    for (int z = zh * 32; z < zh * 32 + 32; ++z) {
        acc += pr[z] * __ldg(&vb[(size_t)pix[z] * 64 + col]);
    }
    sc[t] = acc;
    __syncthreads();
    if (t < 64)
        out[(size_t)row * 64 + t] = (sc[t] + sc[t + 64]) / denom;
}

extern "C" void kernel_launch(void* const* d_in, const int* in_sizes, int n_in,
                              void* d_out, int out_size)
{
    const float* q = (const float*)d_in[0];   // (8, 512, 64)
    const float* k = (const float*)d_in[1];   // (8, 4096, 64)
    const float* v = (const float*)d_in[2];   // (8, 4096, 64)
    float* out = (float*)d_out;               // (8, 512, 64)
    (void)in_sizes; (void)n_in; (void)out_size;

    tree_attn_kernel<<<8 * 512, 128>>>(q, k, v, out);
}

// round 13
// speedup vs baseline: 1.3947x; 1.0206x over previous
#include <cuda_runtime.h>
#include <cstdint>

// TreeAttention: N=8, T_DST=512, T_SRC=4096, HID=64, K=64, W0=64,
// SCALE_UP=2, OVERSAMPLE=1.5. One CTA (128 threads) per (n, a) row.
//
// Score caching: child0's gather index equals its parent's BIT-EXACTLY
// (binade scaling it0..4; scale==ratio at it5; ratio=1 at it6), so child0
// scores AND gather indices are copied at placement; only dual children
// (and the initial 64 rows) are gathered, via worklist wl[0..wlcnt).
// Gather passes are skipped per-warp when that warp has no valid rows
// (warp-uniform condition; shfl trees stay converged).
//
// Top-k via 256-bucket histogram MEMBERSHIP select (scores pairwise
// distinct). Child emission is monotone (scale>=1.75, slots ascending)
// => emitted stream already sorted-unique; placement = emit-count scan.
//
// it6 specialized: ws==tsrc -> ratio=1, scale=1, tks=64; final set =
// (top-64 by score ∪ {pixel 0}) truncated to 64 smallest pixels via
// ballot compaction. Softmax max/sum via warp shfl reductions.
// Exactness: rintf, __fdiv_rn/__fmul_rn throughout.

#define NEGV  (-32000.0f)
#define FMINV (-1e30f)

__device__ __forceinline__ unsigned sortable_u(float f) {
    unsigned i = __float_as_uint(f);
    return i ^ ((unsigned)((int)i >> 31) | 0x80000000u);
}

__global__ __launch_bounds__(128, 10)
void tree_attn_kernel(const float* __restrict__ q,
                      const float* __restrict__ k,
                      const float* __restrict__ v,
                      float* __restrict__ out)
{
    const int row  = blockIdx.x;          // n*512 + a
    const int n    = row >> 9;
    const int a    = row & 511;
    const int t    = threadIdx.x;         // 0..127
    const int lane = t & 31;
    const int wid  = t >> 5;
    const int c8   = t & 7;               // chunk within row (8 threads/row)
    const int or8  = t >> 3;              // row slot (0..15)

    __shared__ __align__(16) float qs[64];
    __shared__ __align__(16) float sc[128];
    __shared__ __align__(16) float pr[64];
    __shared__ int      pix[128];
    __shared__ int      xs[128];          // gather indices
    __shared__ __align__(16) int hist[256];
    __shared__ unsigned cand1[128];
    __shared__ unsigned cand2[128];
    __shared__ int      wl[128];          // uncached-slot worklist
    __shared__ int      wlcnt;
    __shared__ int      wsum[4];
    __shared__ float    fsum[4];
    __shared__ int      sel[7];           // bs1,m1,bs2,m2,cnt1,cnt2,extra

    const float  tsrc = (float)(3585 + a);        // T_SRC - T_DST + 1 + a
    const float* kb   = k + (size_t)n * (4096 * 64);

    if (t < 64) qs[t] = q[(size_t)row * 64 + t];
    {
        const float r0 = __fdiv_rn(tsrc, 64.0f);
        const int   p  = (t < 96) ? t : 0;
        pix[t] = p;
        xs[t]  = min((int)rintf(__fmul_rn((float)p, r0)), 4095);
    }
    if (t < 64) wl[t] = t;                // initial rows all uncached
    if (t == 0) wlcnt = 64;
    __syncthreads();

    const float4 qa = ((const float4*)qs)[c8];
    const float4 qb = ((const float4*)qs)[c8 + 8];

    float ws = 64.0f;
    int   V  = 64;                        // valid prefix length (shared-state)

    #pragma unroll 1
    for (int it = 0; it < 6; ++it) {
        const int tks_max = (it == 0) ? 63 : 96;
        const int Zcur    = (it == 0) ? 96 : 128;

        // ---- A: gather ONLY uncached rows (worklist); zero hist ----
        const int U = wlcnt;              // read before any thread passes B1
        if (t >= V) sc[t] = NEGV;
        ((int2*)hist)[t] = make_int2(0, 0);
        if (t < 2) sel[4 + t] = 0;
        #pragma unroll 1
        for (int base = 0; base < U; base += 32) {
            if (base + (wid << 2) < U) {  // warp-uniform: this warp has rows
                const int  i0 = base + or8;
                const int  i1 = base + 16 + or8;
                const bool v0 = (i0 < U);
                const bool v1 = (i1 < U);
                const int  r0 = v0 ? wl[i0] : 0;
                const int  r1 = v1 ? wl[i1] : 0;
                float acc0 = 0.0f, acc1 = 0.0f;
                if (v0) {
                    const float4* kr = (const float4*)(kb + (size_t)xs[r0] * 64);
                    const float4 A = __ldg(kr + c8);
                    const float4 B = __ldg(kr + c8 + 8);
                    acc0  = A.x*qa.x + A.y*qa.y + A.z*qa.z + A.w*qa.w;
                    acc0 += B.x*qb.x + B.y*qb.y + B.z*qb.z + B.w*qb.w;
                }
                if (v1) {
                    const float4* kr = (const float4*)(kb + (size_t)xs[r1] * 64);
                    const float4 A = __ldg(kr + c8);
                    const float4 B = __ldg(kr + c8 + 8);
                    acc1  = A.x*qa.x + A.y*qa.y + A.z*qa.z + A.w*qa.w;
                    acc1 += B.x*qb.x + B.y*qb.y + B.z*qb.z + B.w*qb.w;
                }
                acc0 += __shfl_xor_sync(0xFFFFFFFFu, acc0, 1);
                acc1 += __shfl_xor_sync(0xFFFFFFFFu, acc1, 1);
                acc0 += __shfl_xor_sync(0xFFFFFFFFu, acc0, 2);
                acc1 += __shfl_xor_sync(0xFFFFFFFFu, acc1, 2);
                acc0 += __shfl_xor_sync(0xFFFFFFFFu, acc0, 4);
                acc1 += __shfl_xor_sync(0xFFFFFFFFu, acc1, 4);
                if (v0 && c8 == 0) sc[r0] = acc0;
                if (v1 && c8 == 0) sc[r1] = acc1;
            }
        }
        __syncthreads();                                     // B1
        if (t == 0) wlcnt = 0;            // safe: all reads of wl/U done

        // uniform params
        float tkf = rintf(__fmul_rn(__fmul_rn(__fdiv_rn(ws, tsrc), 64.0f), 1.5f));
        tkf = fminf(fmaxf(tkf, 1.0f), fminf(ws - 1.0f, (float)(Zcur - 1)));
        const int  k1     = min((int)tkf, tks_max);          // dual top-k
        const int  k2     = tks_max;                         // winner top-k
        const bool needK2 = (V > tks_max);
        const float wsn   = fminf(tsrc, __fmul_rn(ws, 2.0f));
        const float scale = __fdiv_rn(wsn, ws);

        const bool     valid  = (t < V);
        const float    sv     = sc[t];
        const int      myx    = xs[t];    // inherited by child0 (bit-exact)
        const unsigned u      = valid ? sortable_u(sv) : 0u;
        const int      bucket = (int)(u >> 24);
        if (valid) atomicAdd(&hist[bucket], 1);
        __syncthreads();                                     // B2

        // warp 0: descending suffix scan + crossing buckets
        if (wid == 0) {
            const int  base4 = 248 - (lane << 3);
            const int4 A4 = *(const int4*)&hist[base4];
            const int4 B4 = *(const int4*)&hist[base4 + 4];
            const int  s  = A4.x+A4.y+A4.z+A4.w + B4.x+B4.y+B4.z+B4.w;
            int incl0 = s;
            #pragma unroll
            for (int d = 1; d < 32; d <<= 1) {
                const int o = __shfl_up_sync(0xFFFFFFFFu, incl0, d);
                if (lane >= d) incl0 += o;
            }
            int run = incl0 - s;
            const int hh[8] = {B4.w, B4.z, B4.y, B4.x, A4.w, A4.z, A4.y, A4.x};
            #pragma unroll
            for (int j = 0; j < 8; ++j) {
                const int b = 255 - ((lane << 3) + j);
                const int h = hh[j];
                if (run < k1 && run + h >= k1) { sel[0] = b; sel[1] = run; }
                if (needK2 && run < k2 && run + h >= k2) { sel[2] = b; sel[3] = run; }
                run += h;
            }
        }
        __syncthreads();                                     // B3

        const bool c1 = valid && (bucket == sel[0]);
        if (c1) cand1[atomicAdd(&sel[4], 1)] = u;
        const bool c2 = needK2 && valid && (bucket == sel[2]);
        if (c2) cand2[atomicAdd(&sel[5], 1)] = u;
        __syncthreads();                                     // B4

        // ---- membership + monotone child emission ----
        bool winner = valid, dual = false;
        if (valid) {
            if (bucket > sel[0]) dual = true;
            else if (c1) {
                const int C = sel[4];
                int r = 0;
                for (int j = 0; j < C; ++j) r += (int)(cand1[j] > u);
                dual = (r < k1 - sel[1]);
            }
            if (needK2) {
                if (bucket > sel[2]) winner = true;
                else if (c2) {
                    const int C = sel[5];
                    int r = 0;
                    for (int j = 0; j < C; ++j) r += (int)(cand2[j] > u);
                    winner = (r < k2 - sel[3]);
                } else winner = false;
            }
        }
        int e = 0, p0 = 0;
        if (winner) {
            const float pf = (float)pix[t];
            p0 = min((int)rintf(__fmul_rn(pf, scale)), 4095);
            e = 1;
            if (dual) {
                const int p1 = (int)rintf(__fmul_rn(pf + 1.0f, scale));
                if (p1 - p0 >= 2) e = 2;
            }
        }
        int incl = e;
        #pragma unroll
        for (int d = 1; d < 32; d <<= 1) {
            const int o = __shfl_up_sync(0xFFFFFFFFu, incl, d);
            if (lane >= d) incl += o;
        }
        if (lane == 31) wsum[wid] = incl;
        if (t == 0) sel[6] = winner ? 0 : 1;
        __syncthreads();                                     // B5

        const int extra = sel[6];
        int base2 = extra, total = extra;
        #pragma unroll
        for (int w2 = 0; w2 < 4; ++w2) {
            const int s = wsum[w2];
            if (w2 < wid) base2 += s;
            total += s;
        }
        const float ratio_n = __fdiv_rn(tsrc, wsn);
        const int pos = base2 + incl - e;                    // exclusive
        // prepended pixel-0: sc[0] already holds q.k[0] (slot-0 invariant)
        if (extra && t == 0) { pix[0] = 0; xs[0] = 0; }
        if (e >= 1 && pos < 128) {
            pix[pos] = p0;
            xs[pos]  = myx;               // bit-exact: x_child0 == x_parent
            sc[pos]  = sv;                // cached score
        }
        if (e == 2 && pos + 1 < 128) {
            const int pv = p0 + 1;
            pix[pos + 1] = pv;
            xs[pos + 1]  = min((int)rintf(__fmul_rn((float)pv, ratio_n)), 4095);
            wl[atomicAdd(&wlcnt, 1)] = pos + 1;   // uncached: gather next iter
        }
        const int Vn = min(total, 128);
        if (t >= Vn) { pix[t] = 0; xs[t] = 0; }
        __syncthreads();                                     // B6

        V  = Vn;
        ws = wsn;
    }

    // ==== it6 (ws==tsrc: ratio=1, scale=1, tks=64): top-64 membership ====
    {
        const int U = wlcnt;
        ((int2*)hist)[t] = make_int2(0, 0);
        if (t == 0) sel[4] = 0;
        #pragma unroll 1
        for (int base = 0; base < U; base += 32) {
            if (base + (wid << 2) < U) {
                const int  i0 = base + or8;
                const int  i1 = base + 16 + or8;
                const bool v0 = (i0 < U);
                const bool v1 = (i1 < U);
                const int  r0 = v0 ? wl[i0] : 0;
                const int  r1 = v1 ? wl[i1] : 0;
                float acc0 = 0.0f, acc1 = 0.0f;
                if (v0) {
                    const float4* kr = (const float4*)(kb + (size_t)xs[r0] * 64);
                    const float4 A = __ldg(kr + c8);
                    const float4 B = __ldg(kr + c8 + 8);
                    acc0  = A.x*qa.x + A.y*qa.y + A.z*qa.z + A.w*qa.w;
                    acc0 += B.x*qb.x + B.y*qb.y + B.z*qb.z + B.w*qb.w;
                }
                if (v1) {
                    const float4* kr = (const float4*)(kb + (size_t)xs[r1] * 64);
                    const float4 A = __ldg(kr + c8);
                    const float4 B = __ldg(kr + c8 + 8);
                    acc1  = A.x*qa.x + A.y*qa.y + A.z*qa.z + A.w*qa.w;
                    acc1 += B.x*qb.x + B.y*qb.y + B.z*qb.z + B.w*qb.w;
                }
                acc0 += __shfl_xor_sync(0xFFFFFFFFu, acc0, 1);
                acc1 += __shfl_xor_sync(0xFFFFFFFFu, acc1, 1);
                acc0 += __shfl_xor_sync(0xFFFFFFFFu, acc0, 2);
                acc1 += __shfl_xor_sync(0xFFFFFFFFu, acc1, 2);
                acc0 += __shfl_xor_sync(0xFFFFFFFFu, acc0, 4);
                acc1 += __shfl_xor_sync(0xFFFFFFFFu, acc1, 4);
                if (v0 && c8 == 0) sc[r0] = acc0;
                if (v1 && c8 == 0) sc[r1] = acc1;
            }
        }
        __syncthreads();                                     // C1

        const bool     valid  = (t < V);
        const float    sv     = valid ? sc[t] : FMINV;
        const unsigned u      = valid ? sortable_u(sv) : 0u;
        const int      bucket = (int)(u >> 24);
        if (valid) atomicAdd(&hist[bucket], 1);
        __syncthreads();                                     // C2

        if (wid == 0) {
            const int  base4 = 248 - (lane << 3);
            const int4 A4 = *(const int4*)&hist[base4];
            const int4 B4 = *(const int4*)&hist[base4 + 4];
            const int  s  = A4.x+A4.y+A4.z+A4.w + B4.x+B4.y+B4.z+B4.w;
            int incl0 = s;
            #pragma unroll
            for (int d = 1; d < 32; d <<= 1) {
                const int o = __shfl_up_sync(0xFFFFFFFFu, incl0, d);
                if (lane >= d) incl0 += o;
            }
            int run = incl0 - s;
            const int hh[8] = {B4.w, B4.z, B4.y, B4.x, A4.w, A4.z, A4.y, A4.x};
            #pragma unroll
            for (int j = 0; j < 8; ++j) {
                const int b = 255 - ((lane << 3) + j);
                const int h = hh[j];
                if (run < 64 && run + h >= 64) { sel[0] = b; sel[1] = run; }
                run += h;
            }
        }
        __syncthreads();                                     // C3

        const bool c1 = valid && (bucket == sel[0]);
        if (c1) cand1[atomicAdd(&sel[4], 1)] = u;
        __syncthreads();                                     // C4

        bool member = false;
        if (valid) {
            if (bucket > sel[0]) member = true;
            else if (c1) {
                const int C = sel[4];
                int r = 0;
                for (int j = 0; j < C; ++j) r += (int)(cand1[j] > u);
                member = (r < 64 - sel[1]);
            }
        }
        const bool  win = (t == 0) || member;   // slot 0 = pixel 0 pad
        const int   myp = pix[t];
        const float mys = sv;
        const unsigned wb = __ballot_sync(0xFFFFFFFFu, win);
        if (lane == 0) wsum[wid] = __popc(wb);
        __syncthreads();                                     // C5

        int wbase = 0, total = 0;
        #pragma unroll
        for (int w2 = 0; w2 < 4; ++w2) {
            const int s = wsum[w2];
            if (w2 < wid) wbase += s;
            total += s;
        }
        const int cnt = min(total, 64);
        const int pos = wbase + __popc(wb & ((1u << lane) - 1u));
        // slots pixel-ascending; keep the 64 smallest pixel values
        if (win && pos < 64) { pix[pos] = myp; sc[pos] = mys; }
        if (t >= cnt && t < 64) { pix[t] = 0; sc[t] = FMINV; }
        __syncthreads();                                     // C6
    }

    // ---- softmax via shfl reductions (warps 0-1 hold the 64 scores) ----
    float ex = 0.0f;
    if (t < 64) {
        float m = sc[t];
        #pragma unroll
        for (int d = 16; d >= 1; d >>= 1)
            m = fmaxf(m, __shfl_xor_sync(0xFFFFFFFFu, m, d));
        if (lane == 0) fsum[wid] = m;
    }
    __syncthreads();
    if (t < 64) {
        const float mx = fmaxf(fsum[0], fsum[1]);
        ex = __expf(sc[t] - mx);
        pr[t] = ex;
        float s = ex;
        #pragma unroll
        for (int d = 16; d >= 1; d >>= 1)
            s += __shfl_xor_sync(0xFFFFFFFFu, s, d);
        if (lane == 0) fsum[2 + wid] = s;
    }
    __syncthreads();
    const float denom = fsum[2] + fsum[3];

    // ---- weighted V gather: 128 threads = 64 cols x 2 z-halves ----
    const float* vb  = v + (size_t)n * (4096 * 64);
    const int    col = t & 63;
    const int    zh  = t >> 6;
    float acc = 0.0f;
    #pragma unroll 4
    for (int z = zh * 32; z < zh * 32 + 32; ++z) {
        acc += pr[z] * __ldg(&vb[(size_t)pix[z] * 64 + col]);
    }
    sc[t] = acc;
    __syncthreads();
    if (t < 64)
        out[(size_t)row * 64 + t] = (sc[t] + sc[t + 64]) / denom;
}

extern "C" void kernel_launch(void* const* d_in, const int* in_sizes, int n_in,
                              void* d_out, int out_size)
{
    const float* q = (const float*)d_in[0];   // (8, 512, 64)
    const float* k = (const float*)d_in[1];   // (8, 4096, 64)
    const float* v = (const float*)d_in[2];   // (8, 4096, 64)
    float* out = (float*)d_out;               // (8, 512, 64)
    (void)in_sizes; (void)n_in; (void)out_size;

    tree_attn_kernel<<<8 * 512, 128>>>(q, k, v, out);
}

// round 14
// speedup vs baseline: 1.4617x; 1.0481x over previous
#include <cuda_runtime.h>
#include <cstdint>

// TreeAttention: N=8, T_DST=512, T_SRC=4096, HID=64, K=64, W0=64,
// SCALE_UP=2, OVERSAMPLE=1.5. One CTA (128 threads) per (n, a) row.
//
// Score caching: child0's gather index equals its parent's BIT-EXACTLY,
// so child0 scores AND gather indices are copied at placement; only dual
// children (and the initial 64 rows) are gathered via worklist wl.
//
// Exact-arithmetic specializations (all bit-identical to the reference):
//  - it0..4: scale == 2.0 exactly  -> child0 = 2p (integer), dual always
//    emits p0+1; pixels < ws inductively so clamps never bind.
//  - ratio_n = tsrc / 2^k  == __fmul_rn(tsrc, 2^-k) (exact scaling).
//  - it5: scale = tsrc*2^-11 (exact); ratio_n == 1 -> dual xs = pv.
//  - only the reference's ws/tsrc division remains per iteration.
//
// Top-k via 256-bucket histogram MEMBERSHIP select (scores pairwise
// distinct); monotone child emission => stream already sorted-unique.
// it6: final set = (top-64 ∪ {pixel 0}) truncated to 64 smallest pixels
// via ballot compaction. AV gather: float4 warp-cooperative, reduction
// through smem (reusing hist).

#define NEGV  (-32000.0f)
#define FMINV (-1e30f)

__device__ __forceinline__ unsigned sortable_u(float f) {
    unsigned i = __float_as_uint(f);
    return i ^ ((unsigned)((int)i >> 31) | 0x80000000u);
}

__global__ __launch_bounds__(128, 10)
void tree_attn_kernel(const float* __restrict__ q,
                      const float* __restrict__ k,
                      const float* __restrict__ v,
                      float* __restrict__ out)
{
    const int row  = blockIdx.x;          // n*512 + a
    const int n    = row >> 9;
    const int a    = row & 511;
    const int t    = threadIdx.x;         // 0..127
    const int lane = t & 31;
    const int wid  = t >> 5;
    const int c8   = t & 7;               // chunk within row (8 threads/row)
    const int or8  = t >> 3;              // row slot (0..15)

    __shared__ __align__(16) float qs[64];
    __shared__ __align__(16) float sc[128];
    __shared__ __align__(16) float pr[64];
    __shared__ int      pix[128];
    __shared__ int      xs[128];          // gather indices
    __shared__ __align__(16) int hist[256];   // also reused as float4[64]
    __shared__ unsigned cand1[128];
    __shared__ unsigned cand2[128];
    __shared__ int      wl[128];          // uncached-slot worklist
    __shared__ int      wlcnt;
    __shared__ int      wsum[4];
    __shared__ float    fsum[4];
    __shared__ int      sel[7];           // bs1,m1,bs2,m2,cnt1,cnt2,extra

    const float  tsrc = (float)(3585 + a);        // T_SRC - T_DST + 1 + a
    const float* kb   = k + (size_t)n * (4096 * 64);

    if (t < 64) qs[t] = q[(size_t)row * 64 + t];
    {
        const float r0 = __fmul_rn(tsrc, 0.015625f);  // tsrc/64 exact
        const int   p  = (t < 96) ? t : 0;
        pix[t] = p;
        xs[t]  = min((int)rintf(__fmul_rn((float)p, r0)), 4095);
    }
    if (t < 64) wl[t] = t;                // initial rows all uncached
    if (t == 0) wlcnt = 64;
    __syncthreads();

    const float4 qa = ((const float4*)qs)[c8];
    const float4 qb = ((const float4*)qs)[c8 + 8];

    float ws = 64.0f;
    int   V  = 64;                        // valid prefix length (shared-state)

    #pragma unroll 1
    for (int it = 0; it < 6; ++it) {
        const int tks_max = (it == 0) ? 63 : 96;
        const int Zcur    = (it == 0) ? 96 : 128;

        // ---- A: gather ONLY uncached rows (worklist); zero hist ----
        const int U = wlcnt;              // read before any thread passes B1
        if (t >= V) sc[t] = NEGV;
        ((int2*)hist)[t] = make_int2(0, 0);
        if (t < 2) sel[4 + t] = 0;
        #pragma unroll 1
        for (int base = 0; base < U; base += 32) {
            if (base + (wid << 2) < U) {  // warp-uniform: this warp has rows
                const int  i0 = base + or8;
                const int  i1 = base + 16 + or8;
                const bool v0 = (i0 < U);
                const bool v1 = (i1 < U);
                const int  r0 = v0 ? wl[i0] : 0;
                const int  r1 = v1 ? wl[i1] : 0;
                float acc0 = 0.0f, acc1 = 0.0f;
                if (v0) {
                    const float4* kr = (const float4*)(kb + (size_t)xs[r0] * 64);
                    const float4 A = __ldg(kr + c8);
                    const float4 B = __ldg(kr + c8 + 8);
                    acc0  = A.x*qa.x + A.y*qa.y + A.z*qa.z + A.w*qa.w;
                    acc0 += B.x*qb.x + B.y*qb.y + B.z*qb.z + B.w*qb.w;
                }
                if (v1) {
                    const float4* kr = (const float4*)(kb + (size_t)xs[r1] * 64);
                    const float4 A = __ldg(kr + c8);
                    const float4 B = __ldg(kr + c8 + 8);
                    acc1  = A.x*qa.x + A.y*qa.y + A.z*qa.z + A.w*qa.w;
                    acc1 += B.x*qb.x + B.y*qb.y + B.z*qb.z + B.w*qb.w;
                }
                acc0 += __shfl_xor_sync(0xFFFFFFFFu, acc0, 1);
                acc1 += __shfl_xor_sync(0xFFFFFFFFu, acc1, 1);
                acc0 += __shfl_xor_sync(0xFFFFFFFFu, acc0, 2);
                acc1 += __shfl_xor_sync(0xFFFFFFFFu, acc1, 2);
                acc0 += __shfl_xor_sync(0xFFFFFFFFu, acc0, 4);
                acc1 += __shfl_xor_sync(0xFFFFFFFFu, acc1, 4);
                if (v0 && c8 == 0) sc[r0] = acc0;
                if (v1 && c8 == 0) sc[r1] = acc1;
            }
        }
        __syncthreads();                                     // B1
        if (t == 0) wlcnt = 0;            // safe: all reads of wl/U done

        // uniform params (single remaining fdiv: reference's ws/tsrc)
        float tkf = rintf(__fmul_rn(__fmul_rn(__fdiv_rn(ws, tsrc), 64.0f), 1.5f));
        tkf = fminf(fmaxf(tkf, 1.0f), fminf(ws - 1.0f, (float)(Zcur - 1)));
        const int  k1     = min((int)tkf, tks_max);          // dual top-k
        const int  k2     = tks_max;                         // winner top-k
        const bool needK2 = (V > tks_max);
        const bool pow2it = (it < 5);
        const float wsn   = pow2it ? __fmul_rn(ws, 2.0f) : tsrc;
        // ratio_n = tsrc / wsn: exact power-of-2 scaling for it<5; 1.0 at it5
        const float ratio_n = pow2it
            ? __fmul_rn(tsrc, __uint_as_float((unsigned)(120 - it) << 23))
            : 1.0f;

        const bool     valid  = (t < V);
        const float    sv     = sc[t];
        const int      myx    = xs[t];    // inherited by child0 (bit-exact)
        const unsigned u      = valid ? sortable_u(sv) : 0u;
        const int      bucket = (int)(u >> 24);
        if (valid) atomicAdd(&hist[bucket], 1);
        __syncthreads();                                     // B2

        // warp 0: descending suffix scan + crossing buckets
        if (wid == 0) {
            const int  base4 = 248 - (lane << 3);
            const int4 A4 = *(const int4*)&hist[base4];
            const int4 B4 = *(const int4*)&hist[base4 + 4];
            const int  s  = A4.x+A4.y+A4.z+A4.w + B4.x+B4.y+B4.z+B4.w;
            int incl0 = s;
            #pragma unroll
            for (int d = 1; d < 32; d <<= 1) {
                const int o = __shfl_up_sync(0xFFFFFFFFu, incl0, d);
                if (lane >= d) incl0 += o;
            }
            int run = incl0 - s;
            const int hh[8] = {B4.w, B4.z, B4.y, B4.x, A4.w, A4.z, A4.y, A4.x};
            #pragma unroll
            for (int j = 0; j < 8; ++j) {
                const int b = 255 - ((lane << 3) + j);
                const int h = hh[j];
                if (run < k1 && run + h >= k1) { sel[0] = b; sel[1] = run; }
                if (needK2 && run < k2 && run + h >= k2) { sel[2] = b; sel[3] = run; }
                run += h;
            }
        }
        __syncthreads();                                     // B3

        const bool c1 = valid && (bucket == sel[0]);
        if (c1) cand1[atomicAdd(&sel[4], 1)] = u;
        const bool c2 = needK2 && valid && (bucket == sel[2]);
        if (c2) cand2[atomicAdd(&sel[5], 1)] = u;
        __syncthreads();                                     // B4

        // ---- membership + monotone child emission ----
        bool winner = valid, dual = false;
        if (valid) {
            if (bucket > sel[0]) dual = true;
            else if (c1) {
                const int C = sel[4];
                int r = 0;
                for (int j = 0; j < C; ++j) r += (int)(cand1[j] > u);
                dual = (r < k1 - sel[1]);
            }
            if (needK2) {
                if (bucket > sel[2]) winner = true;
                else if (c2) {
                    const int C = sel[5];
                    int r = 0;
                    for (int j = 0; j < C; ++j) r += (int)(cand2[j] > u);
                    winner = (r < k2 - sel[3]);
                } else winner = false;
            }
        }
        int e = 0, p0 = 0;
        if (winner) {
            if (pow2it) {
                p0 = pix[t] << 1;         // scale == 2.0 exact; no clamp binds
                e  = dual ? 2 : 1;        // p1-p0 == 2 always
            } else {                      // it5: scale = tsrc*2^-11 exact
                const float scale = __fmul_rn(tsrc, 4.8828125e-4f);
                const float pf = (float)pix[t];
                p0 = min((int)rintf(__fmul_rn(pf, scale)), 4095);
                e = 1;
                if (dual) {
                    const int p1 = (int)rintf(__fmul_rn(pf + 1.0f, scale));
                    if (p1 - p0 >= 2) e = 2;
                }
            }
        }
        int incl = e;
        #pragma unroll
        for (int d = 1; d < 32; d <<= 1) {
            const int o = __shfl_up_sync(0xFFFFFFFFu, incl, d);
            if (lane >= d) incl += o;
        }
        if (lane == 31) wsum[wid] = incl;
        if (t == 0) sel[6] = winner ? 0 : 1;
        __syncthreads();                                     // B5

        const int extra = sel[6];
        int base2 = extra, total = extra;
        #pragma unroll
        for (int w2 = 0; w2 < 4; ++w2) {
            const int s = wsum[w2];
            if (w2 < wid) base2 += s;
            total += s;
        }
        const int pos = base2 + incl - e;                    // exclusive
        // prepended pixel-0: sc[0] already holds q.k[0] (slot-0 invariant)
        if (extra && t == 0) { pix[0] = 0; xs[0] = 0; }
        if (e >= 1 && pos < 128) {
            pix[pos] = p0;
            xs[pos]  = myx;               // bit-exact: x_child0 == x_parent
            sc[pos]  = sv;                // cached score
        }
        if (e == 2 && pos + 1 < 128) {
            const int pv = p0 + 1;
            pix[pos + 1] = pv;
            xs[pos + 1]  = pow2it
                ? min((int)rintf(__fmul_rn((float)pv, ratio_n)), 4095)
                : pv;                     // it5: ratio_n == 1 exactly
            wl[atomicAdd(&wlcnt, 1)] = pos + 1;   // uncached: gather next iter
        }
        const int Vn = min(total, 128);
        if (t >= Vn) { pix[t] = 0; xs[t] = 0; }
        __syncthreads();                                     // B6

        V  = Vn;
        ws = wsn;
    }

    // ==== it6 (ws==tsrc: ratio=1, scale=1, tks=64): top-64 membership ====
    {
        const int U = wlcnt;
        ((int2*)hist)[t] = make_int2(0, 0);
        if (t == 0) sel[4] = 0;
        #pragma unroll 1
        for (int base = 0; base < U; base += 32) {
            if (base + (wid << 2) < U) {
                const int  i0 = base + or8;
                const int  i1 = base + 16 + or8;
                const bool v0 = (i0 < U);
                const bool v1 = (i1 < U);
                const int  r0 = v0 ? wl[i0] : 0;
                const int  r1 = v1 ? wl[i1] : 0;
                float acc0 = 0.0f, acc1 = 0.0f;
                if (v0) {
                    const float4* kr = (const float4*)(kb + (size_t)xs[r0] * 64);
                    const float4 A = __ldg(kr + c8);
                    const float4 B = __ldg(kr + c8 + 8);
                    acc0  = A.x*qa.x + A.y*qa.y + A.z*qa.z + A.w*qa.w;
                    acc0 += B.x*qb.x + B.y*qb.y + B.z*qb.z + B.w*qb.w;
                }
                if (v1) {
                    const float4* kr = (const float4*)(kb + (size_t)xs[r1] * 64);
                    const float4 A = __ldg(kr + c8);
                    const float4 B = __ldg(kr + c8 + 8);
                    acc1  = A.x*qa.x + A.y*qa.y + A.z*qa.z + A.w*qa.w;
                    acc1 += B.x*qb.x + B.y*qb.y + B.z*qb.z + B.w*qb.w;
                }
                acc0 += __shfl_xor_sync(0xFFFFFFFFu, acc0, 1);
                acc1 += __shfl_xor_sync(0xFFFFFFFFu, acc1, 1);
                acc0 += __shfl_xor_sync(0xFFFFFFFFu, acc0, 2);
                acc1 += __shfl_xor_sync(0xFFFFFFFFu, acc1, 2);
                acc0 += __shfl_xor_sync(0xFFFFFFFFu, acc0, 4);
                acc1 += __shfl_xor_sync(0xFFFFFFFFu, acc1, 4);
                if (v0 && c8 == 0) sc[r0] = acc0;
                if (v1 && c8 == 0) sc[r1] = acc1;
            }
        }
        __syncthreads();                                     // C1

        const bool     valid  = (t < V);
        const float    sv     = valid ? sc[t] : FMINV;
        const unsigned u      = valid ? sortable_u(sv) : 0u;
        const int      bucket = (int)(u >> 24);
        if (valid) atomicAdd(&hist[bucket], 1);
        __syncthreads();                                     // C2

        if (wid == 0) {
            const int  base4 = 248 - (lane << 3);
            const int4 A4 = *(const int4*)&hist[base4];
            const int4 B4 = *(const int4*)&hist[base4 + 4];
            const int  s  = A4.x+A4.y+A4.z+A4.w + B4.x+B4.y+B4.z+B4.w;
            int incl0 = s;
            #pragma unroll
            for (int d = 1; d < 32; d <<= 1) {
                const int o = __shfl_up_sync(0xFFFFFFFFu, incl0, d);
                if (lane >= d) incl0 += o;
            }
            int run = incl0 - s;
            const int hh[8] = {B4.w, B4.z, B4.y, B4.x, A4.w, A4.z, A4.y, A4.x};
            #pragma unroll
            for (int j = 0; j < 8; ++j) {
                const int b = 255 - ((lane << 3) + j);
                const int h = hh[j];
                if (run < 64 && run + h >= 64) { sel[0] = b; sel[1] = run; }
                run += h;
            }
        }
        __syncthreads();                                     // C3

        const bool c1 = valid && (bucket == sel[0]);
        if (c1) cand1[atomicAdd(&sel[4], 1)] = u;
        __syncthreads();                                     // C4

        bool member = false;
        if (valid) {
            if (bucket > sel[0]) member = true;
            else if (c1) {
                const int C = sel[4];
                int r = 0;
                for (int j = 0; j < C; ++j) r += (int)(cand1[j] > u);
                member = (r < 64 - sel[1]);
            }
        }
        const bool  win = (t == 0) || member;   // slot 0 = pixel 0 pad
        const int   myp = pix[t];
        const float mys = sv;
        const unsigned wb = __ballot_sync(0xFFFFFFFFu, win);
        if (lane == 0) wsum[wid] = __popc(wb);
        __syncthreads();                                     // C5

        int wbase = 0, total = 0;
        #pragma unroll
        for (int w2 = 0; w2 < 4; ++w2) {
            const int s = wsum[w2];
            if (w2 < wid) wbase += s;
            total += s;
        }
        const int cnt = min(total, 64);
        const int pos = wbase + __popc(wb & ((1u << lane) - 1u));
        // slots pixel-ascending; keep the 64 smallest pixel values
        if (win && pos < 64) { pix[pos] = myp; sc[pos] = mys; }
        if (t >= cnt && t < 64) { pix[t] = 0; sc[t] = FMINV; }
        __syncthreads();                                     // C6
    }

    // ---- softmax via shfl reductions (warps 0-1 hold the 64 scores) ----
    if (t < 64) {
        float m = sc[t];
        #pragma unroll
        for (int d = 16; d >= 1; d >>= 1)
            m = fmaxf(m, __shfl_xor_sync(0xFFFFFFFFu, m, d));
        if (lane == 0) fsum[wid] = m;
    }
    __syncthreads();
    if (t < 64) {
        const float mx = fmaxf(fsum[0], fsum[1]);
        const float ex = __expf(sc[t] - mx);
        pr[t] = ex;
        float s = ex;
        #pragma unroll
        for (int d = 16; d >= 1; d >>= 1)
            s += __shfl_xor_sync(0xFFFFFFFFu, s, d);
        if (lane == 0) fsum[2 + wid] = s;
    }
    __syncthreads();
    const float denom = fsum[2] + fsum[3];

    // ---- AV gather: float4 warp-cooperative (warp owns 16 z-slots) ----
    const float* vb    = v + (size_t)n * (4096 * 64);
    const int    halfl = lane >> 4;       // 0/1: which z of the pair
    const int    col4  = lane & 15;       // float4 column chunk
    float4 acc4 = make_float4(0.0f, 0.0f, 0.0f, 0.0f);
    #pragma unroll
    for (int j = 0; j < 8; ++j) {
        const int   z  = (wid << 4) + (j << 1) + halfl;
        const float w  = pr[z];
        const float4 vv = __ldg((const float4*)(vb + (size_t)pix[z] * 64) + col4);
        acc4.x += w * vv.x;
        acc4.y += w * vv.y;
        acc4.z += w * vv.z;
        acc4.w += w * vv.w;
    }
    acc4.x += __shfl_xor_sync(0xFFFFFFFFu, acc4.x, 16);
    acc4.y += __shfl_xor_sync(0xFFFFFFFFu, acc4.y, 16);
    acc4.z += __shfl_xor_sync(0xFFFFFFFFu, acc4.z, 16);
    acc4.w += __shfl_xor_sync(0xFFFFFFFFu, acc4.w, 16);
    float4* red = (float4*)hist;          // reuse hist: 64 float4 = 1KB
    if (lane < 16) red[(wid << 4) + col4] = acc4;
    __syncthreads();
    if (t < 16) {
        const float4 s0 = red[t];
        const float4 s1 = red[16 + t];
        const float4 s2 = red[32 + t];
        const float4 s3 = red[48 + t];
        float4 o;
        o.x = (s0.x + s1.x + s2.x + s3.x) / denom;
        o.y = (s0.y + s1.y + s2.y + s3.y) / denom;
        o.z = (s0.z + s1.z + s2.z + s3.z) / denom;
        o.w = (s0.w + s1.w + s2.w + s3.w) / denom;
        ((float4*)out)[(size_t)row * 16 + t] = o;
    }
}

extern "C" void kernel_launch(void* const* d_in, const int* in_sizes, int n_in,
                              void* d_out, int out_size)
{
    const float* q = (const float*)d_in[0];   // (8, 512, 64)
    const float* k = (const float*)d_in[1];   // (8, 4096, 64)
    const float* v = (const float*)d_in[2];   // (8, 4096, 64)
    float* out = (float*)d_out;               // (8, 512, 64)
    (void)in_sizes; (void)n_in; (void)out_size;

    tree_attn_kernel<<<8 * 512, 128>>>(q, k, v, out);
}